// round 12
// baseline (speedup 1.0000x reference)
#include <cuda_runtime.h>
#include <cuda_bf16.h>
#include <cuda_fp16.h>
#include <cstdint>

#define NMAX 100000
#define EMAX 1600000

// ---------------- scratch (static device globals; no allocation) ----------------
__device__ int   g_degin [NMAX];
__device__ int   g_degout[NMAX];
__device__ float g_ns[NMAX];
__device__ float g_nd[NMAX];
__device__ int   g_rowptr[NMAX + 1];
__device__ int   g_cursor[NMAX];
__device__ int   g_bsum[256];
__device__ int   g_colidx[EMAX];
__device__ __align__(256) __half g_preh[NMAX * 64];   // fp16 pull payloads
__device__ __align__(256) __half g_h1nh[NMAX * 64];
__device__ __align__(256) __half g_yh  [NMAX * 64];
__device__ __align__(256) float  g_h1  [NMAX * 64];   // fp32 GEMM input

// pack two floats -> fp16x2 in a uint32
__device__ __forceinline__ uint32_t pack_h2(float a, float b) {
    uint32_t lo = (uint32_t)__half_as_ushort(__float2half_rn(a));
    uint32_t hi = (uint32_t)__half_as_ushort(__float2half_rn(b));
    return lo | (hi << 16);
}

// ---------------- small kernels ----------------

__global__ void zero_deg_kernel(int* __restrict__ a, int* __restrict__ b, int N) {
    int i = blockIdx.x * blockDim.x + threadIdx.x;
    if (i < N) { a[i] = 0; b[i] = 0; }
}

__global__ void degree_kernel(const int* __restrict__ src, const int* __restrict__ dst,
                              int* __restrict__ dout, int* __restrict__ din, int E) {
    int e = blockIdx.x * blockDim.x + threadIdx.x;
    if (e >= E) return;
    atomicAdd(&dout[src[e]], 1);
    atomicAdd(&din [dst[e]], 1);
}

// block-level exclusive scan of deg_in -> rowptr partials + block sums; fused norm
__global__ void scan1_kernel(const int* __restrict__ degin, const int* __restrict__ degout,
                             int* __restrict__ rowptr, int* __restrict__ bsum,
                             float* __restrict__ ns, float* __restrict__ nd, int N) {
    __shared__ int s[512];
    int t = threadIdx.x;
    int i = blockIdx.x * 512 + t;
    int v = (i < N) ? degin[i] : 0;
    s[t] = v; __syncthreads();
    for (int off = 1; off < 512; off <<= 1) {
        int u = (t >= off) ? s[t - off] : 0;
        __syncthreads();
        s[t] += u;
        __syncthreads();
    }
    if (i < N) {
        rowptr[i] = s[t] - v;
        nd[i] = rsqrtf((float)max(v, 1));
        ns[i] = rsqrtf((float)max(degout[i], 1));
    }
    if (t == 511) bsum[blockIdx.x] = s[511];
}

// finalize rowptr: every block scans the (<=256) block sums locally, applies offset
__global__ void scan3_kernel(int* __restrict__ rowptr, int* __restrict__ cursor,
                             const int* __restrict__ bsum, int nb, int N, int E) {
    __shared__ int sb[256];
    int t = threadIdx.x;
    int v = (t < nb) ? bsum[t] : 0;
    sb[t] = v; __syncthreads();
    for (int off = 1; off < 256; off <<= 1) {
        int u = (t >= off) ? sb[t - off] : 0;
        __syncthreads();
        sb[t] += u;
        __syncthreads();
    }
    int ex = sb[t] - v;
    __syncthreads();
    sb[t] = ex;
    __syncthreads();
    int i = blockIdx.x * blockDim.x + threadIdx.x;
    if (i < N) {
        int r = rowptr[i] + sb[i >> 9];
        rowptr[i] = r;
        cursor[i] = r;
    }
    if (i == 0) rowptr[N] = E;
}

__global__ void csrfill_kernel(const int* __restrict__ src, const int* __restrict__ dst,
                               int* __restrict__ cursor, int* __restrict__ colidx, int E) {
    int e = blockIdx.x * blockDim.x + threadIdx.x;
    if (e >= E) return;
    int slot = atomicAdd(&cursor[dst[e]], 1);
    colidx[slot] = src[e];
}

// ================= split-bf16 mma.sync GEMM pieces (compute_100-legal) =================

__device__ __forceinline__ void mma_bf16(float* c, const uint32_t* a, const uint32_t* b) {
    asm volatile(
        "mma.sync.aligned.m16n8k16.row.col.f32.bf16.bf16.f32 "
        "{%0,%1,%2,%3}, {%4,%5,%6,%7}, {%8,%9}, {%0,%1,%2,%3};"
        : "+f"(c[0]), "+f"(c[1]), "+f"(c[2]), "+f"(c[3])
        : "r"(a[0]), "r"(a[1]), "r"(a[2]), "r"(a[3]), "r"(b[0]), "r"(b[1]));
}

__device__ __forceinline__ void cvt_pair(float f0, float f1, uint32_t& hi, uint32_t& lo) {
    __nv_bfloat16 h0 = __float2bfloat16(f0);
    __nv_bfloat16 h1 = __float2bfloat16(f1);
    __nv_bfloat16 l0 = __float2bfloat16(f0 - __bfloat162float(h0));
    __nv_bfloat16 l1 = __float2bfloat16(f1 - __bfloat162float(h1));
    hi = (uint32_t)__bfloat16_as_ushort(h0) | ((uint32_t)__bfloat16_as_ushort(h1) << 16);
    lo = (uint32_t)__bfloat16_as_ushort(l0) | ((uint32_t)__bfloat16_as_ushort(l1) << 16);
}

// layer-1 GEMM: preh[N,64] = fp16( (feats*ns)[N,128] @ W1[128,64] )
__global__ void __launch_bounds__(256)
gemm1_kernel(const float* __restrict__ A, const float* __restrict__ W,
             const float* __restrict__ ns, __half* __restrict__ outh, int N) {
    extern __shared__ uint32_t sm[];
    constexpr int K = 128, P = K / 2 + 4, K4 = K / 4;
    uint32_t* sAh = sm;
    uint32_t* sAl = sm + 128 * P;
    uint32_t* sBh = sm + 256 * P;
    uint32_t* sBl = sm + 256 * P + 64 * P;

    const int tid = threadIdx.x;
    const int wid = tid >> 5, lane = tid & 31;
    const int gid = lane >> 2, t = lane & 3;
    const int n0 = blockIdx.x * 128;

    for (int idx = tid; idx < 128 * K4; idx += 256) {
        int m = idx / K4, f = idx % K4;
        int node = n0 + m;
        float4 v = make_float4(0.f, 0.f, 0.f, 0.f);
        if (node < N) {
            v = reinterpret_cast<const float4*>(A + (size_t)node * K)[f];
            float s = ns[node];
            v.x *= s; v.y *= s; v.z *= s; v.w *= s;
        }
        uint32_t h0, l0, h1, l1;
        cvt_pair(v.x, v.y, h0, l0);
        cvt_pair(v.z, v.w, h1, l1);
        int o = m * P + f * 2;
        sAh[o] = h0; sAh[o + 1] = h1;
        sAl[o] = l0; sAl[o + 1] = l1;
    }
    for (int idx = tid; idx < 64 * (K / 2); idx += 256) {
        int n = idx & 63, kp = idx >> 6;
        uint32_t h, l;
        cvt_pair(W[(size_t)(2 * kp) * 64 + n], W[(size_t)(2 * kp + 1) * 64 + n], h, l);
        sBh[n * P + kp] = h; sBl[n * P + kp] = l;
    }
    __syncthreads();

    float acc[8][4];
#pragma unroll
    for (int nt = 0; nt < 8; nt++)
#pragma unroll
        for (int j = 0; j < 4; j++) acc[nt][j] = 0.f;

    const int r0 = wid * 16 + gid;
#pragma unroll
    for (int ks = 0; ks < K / 16; ks++) {
        int kb = ks * 8;
        uint32_t ah[4], al[4];
        ah[0] = sAh[ r0      * P + kb + t];
        ah[1] = sAh[(r0 + 8) * P + kb + t];
        ah[2] = sAh[ r0      * P + kb + 4 + t];
        ah[3] = sAh[(r0 + 8) * P + kb + 4 + t];
        al[0] = sAl[ r0      * P + kb + t];
        al[1] = sAl[(r0 + 8) * P + kb + t];
        al[2] = sAl[ r0      * P + kb + 4 + t];
        al[3] = sAl[(r0 + 8) * P + kb + 4 + t];
#pragma unroll
        for (int nt = 0; nt < 8; nt++) {
            int n = nt * 8 + gid;
            uint32_t bh[2], bl[2];
            bh[0] = sBh[n * P + kb + t];
            bh[1] = sBh[n * P + kb + 4 + t];
            bl[0] = sBl[n * P + kb + t];
            bl[1] = sBl[n * P + kb + 4 + t];
            mma_bf16(acc[nt], ah, bh);
            mma_bf16(acc[nt], ah, bl);
            mma_bf16(acc[nt], al, bh);
        }
    }

    const int node0 = n0 + r0, node1 = node0 + 8;
#pragma unroll
    for (int nt = 0; nt < 8; nt++) {
        int col = nt * 8 + t * 2;
        if (node0 < N)
            *reinterpret_cast<uint32_t*>(outh + (size_t)node0 * 64 + col) = pack_h2(acc[nt][0], acc[nt][1]);
        if (node1 < N)
            *reinterpret_cast<uint32_t*>(outh + (size_t)node1 * 64 + col) = pack_h2(acc[nt][2], acc[nt][3]);
    }
}

// fused layers 2+3 WITH integrated pull:
//   sPull = pull(h1nh) for this block's 128 nodes (smem, fp32)
//   h2 = relu((sPull@W2)*nd + b2) [regs];  yh = fp16( [h1|h2] @ Wout )
__global__ void __launch_bounds__(256)
gemm23_kernel(const __half* __restrict__ h1nh,
              const int* __restrict__ rowptr, const int* __restrict__ colidx,
              const float* __restrict__ h1,
              const float* __restrict__ W2, const float* __restrict__ b2,
              const float* __restrict__ nd, const float* __restrict__ Wout,
              __half* __restrict__ yh, int N) {
    extern __shared__ uint32_t sm[];
    constexpr int P1 = 64 / 2 + 4;    // 36
    constexpr int P2 = 128 / 2 + 4;   // 68
    constexpr int SPITCH = 68;        // floats per pulled row
    float* sPull = reinterpret_cast<float*>(sm + 384 * P1);   // offset 55296B, 34816B

    const int tid = threadIdx.x;
    const int wid = tid >> 5, lane = tid & 31;
    const int gid = lane >> 2, t = lane & 3;
    const int n0 = blockIdx.x * 128;
    const int r0 = wid * 16 + gid;
    const int node0 = n0 + r0, node1 = node0 + 8;

    // ---------- step 0: pull agg rows for this block's nodes into smem ----------
    {
        const int grp = lane >> 3;    // quarter-warp edge slot
        const int q   = lane & 7;     // uint4 slot in the 64-half row
        for (int i = 0; i < 16; i++) {
            int node = n0 + wid * 16 + i;      // uniform within warp
            if (node >= N) break;
            const int beg = __ldg(&rowptr[node]);
            const int deg = __ldg(&rowptr[node + 1]) - beg;

            float acc[8];
#pragma unroll
            for (int j = 0; j < 8; j++) acc[j] = 0.f;

            int e = 0;
            while (e < deg) {
                int rem   = deg - e;
                int chunk = (rem < 32) ? rem : 32;
                int my = __ldg(&colidx[beg + e + ((lane < chunk) ? lane : 0)]);
                int nq = (chunk + 3) >> 2;
#pragma unroll 4
                for (int p = 0; p < nq; p++) {
                    int j = 4 * p + grp;
                    bool act = (j < chunk);
                    int s = __shfl_sync(0xffffffffu, my, act ? j : 0);
                    uint4 v = *reinterpret_cast<const uint4*>(h1nh + (size_t)s * 64 + q * 8);
                    if (act) {
                        const __half2* hp = reinterpret_cast<const __half2*>(&v);
                        float2 f0 = __half22float2(hp[0]);
                        float2 f1 = __half22float2(hp[1]);
                        float2 f2 = __half22float2(hp[2]);
                        float2 f3 = __half22float2(hp[3]);
                        acc[0] += f0.x; acc[1] += f0.y;
                        acc[2] += f1.x; acc[3] += f1.y;
                        acc[4] += f2.x; acc[5] += f2.y;
                        acc[6] += f3.x; acc[7] += f3.y;
                    }
                }
                e += chunk;
            }
#pragma unroll
            for (int j = 0; j < 8; j++) {
                acc[j] += __shfl_xor_sync(0xffffffffu, acc[j], 8);
                acc[j] += __shfl_xor_sync(0xffffffffu, acc[j], 16);
            }
            if (grp == 0) {
                float* sp = sPull + (wid * 16 + i) * SPITCH + q * 8;
                reinterpret_cast<float4*>(sp)[0] = make_float4(acc[0], acc[1], acc[2], acc[3]);
                reinterpret_cast<float4*>(sp)[1] = make_float4(acc[4], acc[5], acc[6], acc[7]);
            }
        }
    }
    __syncthreads();

    // ---------- phase 1: acc = sPull @ W2  (K=64) ----------
    {
        uint32_t* sAh = sm;
        uint32_t* sAl = sm + 128 * P1;
        uint32_t* sBh = sm + 256 * P1;
        uint32_t* sBl = sm + 256 * P1 + 64 * P1;

        for (int idx = tid; idx < 128 * 16; idx += 256) {
            int m = idx / 16, f = idx % 16;
            int node = n0 + m;
            float4 v = make_float4(0.f, 0.f, 0.f, 0.f);
            if (node < N) v = *reinterpret_cast<const float4*>(sPull + m * SPITCH + f * 4);
            uint32_t h0, l0, h1v, l1;
            cvt_pair(v.x, v.y, h0, l0);
            cvt_pair(v.z, v.w, h1v, l1);
            int o = m * P1 + f * 2;
            sAh[o] = h0; sAh[o + 1] = h1v;
            sAl[o] = l0; sAl[o + 1] = l1;
        }
        for (int idx = tid; idx < 64 * 32; idx += 256) {
            int n = idx & 63, kp = idx >> 6;
            uint32_t h, l;
            cvt_pair(W2[(size_t)(2 * kp) * 64 + n], W2[(size_t)(2 * kp + 1) * 64 + n], h, l);
            sBh[n * P1 + kp] = h; sBl[n * P1 + kp] = l;
        }
        __syncthreads();

        float acc[8][4];
#pragma unroll
        for (int nt = 0; nt < 8; nt++)
#pragma unroll
            for (int j = 0; j < 4; j++) acc[nt][j] = 0.f;

#pragma unroll
        for (int ks = 0; ks < 4; ks++) {
            int kb = ks * 8;
            uint32_t ah[4], al[4];
            ah[0] = sAh[ r0      * P1 + kb + t];
            ah[1] = sAh[(r0 + 8) * P1 + kb + t];
            ah[2] = sAh[ r0      * P1 + kb + 4 + t];
            ah[3] = sAh[(r0 + 8) * P1 + kb + 4 + t];
            al[0] = sAl[ r0      * P1 + kb + t];
            al[1] = sAl[(r0 + 8) * P1 + kb + t];
            al[2] = sAl[ r0      * P1 + kb + 4 + t];
            al[3] = sAl[(r0 + 8) * P1 + kb + 4 + t];
#pragma unroll
            for (int nt = 0; nt < 8; nt++) {
                int n = nt * 8 + gid;
                uint32_t bh[2], bl[2];
                bh[0] = sBh[n * P1 + kb + t];
                bh[1] = sBh[n * P1 + kb + 4 + t];
                bl[0] = sBl[n * P1 + kb + t];
                bl[1] = sBl[n * P1 + kb + 4 + t];
                mma_bf16(acc[nt], ah, bh);
                mma_bf16(acc[nt], ah, bl);
                mma_bf16(acc[nt], al, bh);
            }
        }

        // epilogue: h2 = relu(acc*nd + b2), restage into phase-2 A (k = 64+col)
        float d0 = (node0 < N) ? nd[node0] : 0.f;
        float d1 = (node1 < N) ? nd[node1] : 0.f;
        float h2v[8][4];
#pragma unroll
        for (int nt = 0; nt < 8; nt++) {
            int col = nt * 8 + t * 2;
            float2 bb = *reinterpret_cast<const float2*>(b2 + col);
            h2v[nt][0] = fmaxf(fmaf(acc[nt][0], d0, bb.x), 0.f);
            h2v[nt][1] = fmaxf(fmaf(acc[nt][1], d0, bb.y), 0.f);
            h2v[nt][2] = fmaxf(fmaf(acc[nt][2], d1, bb.x), 0.f);
            h2v[nt][3] = fmaxf(fmaf(acc[nt][3], d1, bb.y), 0.f);
        }
        __syncthreads();   // phase-1 smem reads done; safe to overwrite

        // ---------- phase 2 staging ----------
        uint32_t* sAh2 = sm;
        uint32_t* sAl2 = sm + 128 * P2;
        uint32_t* sBh2 = sm + 256 * P2;
        uint32_t* sBl2 = sm + 256 * P2 + 64 * P2;

        // h1 part (k 0..63)
        for (int idx = tid; idx < 128 * 16; idx += 256) {
            int m = idx / 16, f = idx % 16;
            int node = n0 + m;
            float4 v = make_float4(0.f, 0.f, 0.f, 0.f);
            if (node < N) v = reinterpret_cast<const float4*>(h1 + (size_t)node * 64)[f];
            uint32_t h0, l0, h1v, l1;
            cvt_pair(v.x, v.y, h0, l0);
            cvt_pair(v.z, v.w, h1v, l1);
            int o = m * P2 + f * 2;
            sAh2[o] = h0; sAh2[o + 1] = h1v;
            sAl2[o] = l0; sAl2[o + 1] = l1;
        }
        // h2 part from registers (k 64..127 -> kp 32..63)
#pragma unroll
        for (int nt = 0; nt < 8; nt++) {
            int kp = 32 + nt * 4 + t;
            uint32_t h, l;
            cvt_pair(h2v[nt][0], h2v[nt][1], h, l);
            sAh2[r0 * P2 + kp] = h; sAl2[r0 * P2 + kp] = l;
            cvt_pair(h2v[nt][2], h2v[nt][3], h, l);
            sAh2[(r0 + 8) * P2 + kp] = h; sAl2[(r0 + 8) * P2 + kp] = l;
        }
        // B = Wout^T (K=128)
        for (int idx = tid; idx < 64 * 64; idx += 256) {
            int n = idx & 63, kp = idx >> 6;
            uint32_t h, l;
            cvt_pair(Wout[(size_t)(2 * kp) * 64 + n], Wout[(size_t)(2 * kp + 1) * 64 + n], h, l);
            sBh2[n * P2 + kp] = h; sBl2[n * P2 + kp] = l;
        }
        __syncthreads();

        // ---------- phase 2 MMA: y = [h1|h2] @ Wout ----------
#pragma unroll
        for (int nt = 0; nt < 8; nt++)
#pragma unroll
            for (int j = 0; j < 4; j++) acc[nt][j] = 0.f;

#pragma unroll
        for (int ks = 0; ks < 8; ks++) {
            int kb = ks * 8;
            uint32_t ah[4], al[4];
            ah[0] = sAh2[ r0      * P2 + kb + t];
            ah[1] = sAh2[(r0 + 8) * P2 + kb + t];
            ah[2] = sAh2[ r0      * P2 + kb + 4 + t];
            ah[3] = sAh2[(r0 + 8) * P2 + kb + 4 + t];
            al[0] = sAl2[ r0      * P2 + kb + t];
            al[1] = sAl2[(r0 + 8) * P2 + kb + t];
            al[2] = sAl2[ r0      * P2 + kb + 4 + t];
            al[3] = sAl2[(r0 + 8) * P2 + kb + 4 + t];
#pragma unroll
            for (int nt = 0; nt < 8; nt++) {
                int n = nt * 8 + gid;
                uint32_t bh[2], bl[2];
                bh[0] = sBh2[n * P2 + kb + t];
                bh[1] = sBh2[n * P2 + kb + 4 + t];
                bl[0] = sBl2[n * P2 + kb + t];
                bl[1] = sBl2[n * P2 + kb + 4 + t];
                mma_bf16(acc[nt], ah, bh);
                mma_bf16(acc[nt], ah, bl);
                mma_bf16(acc[nt], al, bh);
            }
        }

#pragma unroll
        for (int nt = 0; nt < 8; nt++) {
            int col = nt * 8 + t * 2;
            if (node0 < N)
                *reinterpret_cast<uint32_t*>(yh + (size_t)node0 * 64 + col) = pack_h2(acc[nt][0], acc[nt][1]);
            if (node1 < N)
                *reinterpret_cast<uint32_t*>(yh + (size_t)node1 * 64 + col) = pack_h2(acc[nt][2], acc[nt][3]);
        }
    }
}

// ---------------- fp16-payload pull: one warp/node, quarter-warp per edge row ----------------
// EPI: 1 = h = relu(acc*nd + b); o1 = h (fp32); o2 = (h*ns) fp16 payload
//      2 = o1 = acc + b (fp32 output)
template<int EPI>
__global__ void __launch_bounds__(256)
pull_h16_kernel(const __half* __restrict__ tab,
                const int* __restrict__ rowptr, const int* __restrict__ colidx,
                const float* __restrict__ ns, const float* __restrict__ nd,
                const float* __restrict__ b,
                float* __restrict__ o1, __half* __restrict__ o2, int N) {
    int node = (blockIdx.x * blockDim.x + threadIdx.x) >> 5;
    if (node >= N) return;
    const int lane = threadIdx.x & 31;
    const int grp = lane >> 3;
    const int q   = lane & 7;
    const int beg = __ldg(&rowptr[node]);
    const int deg = __ldg(&rowptr[node + 1]) - beg;

    float acc[8];
#pragma unroll
    for (int j = 0; j < 8; j++) acc[j] = 0.f;

    int i = 0;
    while (i < deg) {
        int rem   = deg - i;
        int chunk = (rem < 32) ? rem : 32;
        int my = __ldg(&colidx[beg + i + ((lane < chunk) ? lane : 0)]);
        int nq = (chunk + 3) >> 2;
#pragma unroll 4
        for (int p = 0; p < nq; p++) {
            int j = 4 * p + grp;
            bool act = (j < chunk);
            int s = __shfl_sync(0xffffffffu, my, act ? j : 0);
            uint4 v = *reinterpret_cast<const uint4*>(tab + (size_t)s * 64 + q * 8);
            if (act) {
                const __half2* hp = reinterpret_cast<const __half2*>(&v);
                float2 f0 = __half22float2(hp[0]);
                float2 f1 = __half22float2(hp[1]);
                float2 f2 = __half22float2(hp[2]);
                float2 f3 = __half22float2(hp[3]);
                acc[0] += f0.x; acc[1] += f0.y;
                acc[2] += f1.x; acc[3] += f1.y;
                acc[4] += f2.x; acc[5] += f2.y;
                acc[6] += f3.x; acc[7] += f3.y;
            }
        }
        i += chunk;
    }

#pragma unroll
    for (int j = 0; j < 8; j++) {
        acc[j] += __shfl_xor_sync(0xffffffffu, acc[j], 8);
        acc[j] += __shfl_xor_sync(0xffffffffu, acc[j], 16);
    }
    if (grp != 0) return;

    float* o1p = o1 + (size_t)node * 64 + q * 8;
    if (EPI == 1) {
        float d = nd[node];
        float4 b0 = reinterpret_cast<const float4*>(b + q * 8)[0];
        float4 b1 = reinterpret_cast<const float4*>(b + q * 8)[1];
        float h[8];
        h[0] = fmaxf(fmaf(acc[0], d, b0.x), 0.f);
        h[1] = fmaxf(fmaf(acc[1], d, b0.y), 0.f);
        h[2] = fmaxf(fmaf(acc[2], d, b0.z), 0.f);
        h[3] = fmaxf(fmaf(acc[3], d, b0.w), 0.f);
        h[4] = fmaxf(fmaf(acc[4], d, b1.x), 0.f);
        h[5] = fmaxf(fmaf(acc[5], d, b1.y), 0.f);
        h[6] = fmaxf(fmaf(acc[6], d, b1.z), 0.f);
        h[7] = fmaxf(fmaf(acc[7], d, b1.w), 0.f);
        reinterpret_cast<float4*>(o1p)[0] = make_float4(h[0], h[1], h[2], h[3]);
        reinterpret_cast<float4*>(o1p)[1] = make_float4(h[4], h[5], h[6], h[7]);
        float sn = ns[node];
        uint4 pk;
        pk.x = pack_h2(h[0] * sn, h[1] * sn);
        pk.y = pack_h2(h[2] * sn, h[3] * sn);
        pk.z = pack_h2(h[4] * sn, h[5] * sn);
        pk.w = pack_h2(h[6] * sn, h[7] * sn);
        *reinterpret_cast<uint4*>(o2 + (size_t)node * 64 + q * 8) = pk;
    } else {
        float4 b0 = reinterpret_cast<const float4*>(b + q * 8)[0];
        float4 b1 = reinterpret_cast<const float4*>(b + q * 8)[1];
        reinterpret_cast<float4*>(o1p)[0] =
            make_float4(acc[0] + b0.x, acc[1] + b0.y, acc[2] + b0.z, acc[3] + b0.w);
        reinterpret_cast<float4*>(o1p)[1] =
            make_float4(acc[4] + b1.x, acc[5] + b1.y, acc[6] + b1.z, acc[7] + b1.w);
    }
}

// ---------------- launch ----------------

extern "C" void kernel_launch(void* const* d_in, const int* in_sizes, int n_in,
                              void* d_out, int out_size) {
    const float* feats = (const float*)d_in[0];
    const int*   src   = (const int*)  d_in[1];
    const int*   dst   = (const int*)  d_in[2];
    const float* W1    = (const float*)d_in[3];
    const float* b1    = (const float*)d_in[4];
    const float* W2    = (const float*)d_in[5];
    const float* b2    = (const float*)d_in[6];
    const float* Wout  = (const float*)d_in[7];
    const float* bout  = (const float*)d_in[8];
    float* out = (float*)d_out;

    const int N = in_sizes[0] / 128;
    const int E = in_sizes[1];

    int *p_degin, *p_degout, *p_rowptr, *p_cursor, *p_bsum, *p_colidx;
    float *p_ns, *p_nd, *p_h1;
    __half *p_preh, *p_h1nh, *p_yh;
    cudaGetSymbolAddress((void**)&p_degin,  g_degin);
    cudaGetSymbolAddress((void**)&p_degout, g_degout);
    cudaGetSymbolAddress((void**)&p_rowptr, g_rowptr);
    cudaGetSymbolAddress((void**)&p_cursor, g_cursor);
    cudaGetSymbolAddress((void**)&p_bsum,   g_bsum);
    cudaGetSymbolAddress((void**)&p_colidx, g_colidx);
    cudaGetSymbolAddress((void**)&p_ns,     g_ns);
    cudaGetSymbolAddress((void**)&p_nd,     g_nd);
    cudaGetSymbolAddress((void**)&p_preh,   g_preh);
    cudaGetSymbolAddress((void**)&p_h1nh,   g_h1nh);
    cudaGetSymbolAddress((void**)&p_yh,     g_yh);
    cudaGetSymbolAddress((void**)&p_h1,     g_h1);

    const int TB = 256;
    auto cdiv = [](long long a, long long b) { return (unsigned)((a + b - 1) / b); };
    const int nb = (int)cdiv(N, 512);        // <= 256 for N <= 131072

    const int SMEM_BIG = 384 * (128 / 2 + 4) * 4;   // 104448
    cudaFuncSetAttribute(gemm1_kernel,  cudaFuncAttributeMaxDynamicSharedMemorySize, SMEM_BIG);
    cudaFuncSetAttribute(gemm23_kernel, cudaFuncAttributeMaxDynamicSharedMemorySize, SMEM_BIG);

    // 1-5: degrees, norms, CSR
    zero_deg_kernel<<<cdiv(N, TB), TB>>>(p_degin, p_degout, N);
    degree_kernel  <<<cdiv(E, TB), TB>>>(src, dst, p_degout, p_degin, E);
    scan1_kernel   <<<nb, 512>>>(p_degin, p_degout, p_rowptr, p_bsum, p_ns, p_nd, N);
    scan3_kernel   <<<cdiv(N, TB), TB>>>(p_rowptr, p_cursor, p_bsum, nb, N, E);
    csrfill_kernel <<<cdiv(E, TB), TB>>>(src, dst, p_cursor, p_colidx, E);

    const unsigned mmaGrid  = cdiv(N, 128);
    const unsigned pullGrid = cdiv((long long)N * 32, TB);

    // 6: preh = (feats*ns)@W1 (fp16)
    gemm1_kernel<<<mmaGrid, TB, SMEM_BIG>>>(feats, W1, p_ns, p_preh, N);
    // 7: h1 = relu(pull(preh)*nd + b1); h1nh = (h1*ns) fp16
    pull_h16_kernel<1><<<pullGrid, TB>>>(p_preh, p_rowptr, p_colidx, p_ns, p_nd, b1, p_h1, p_h1nh, N);
    // 8: gemm23 with integrated pull: h2 = relu((pull(h1nh)@W2)*nd+b2); yh = [h1|h2]@Wout
    gemm23_kernel<<<mmaGrid, TB, SMEM_BIG>>>(p_h1nh, p_rowptr, p_colidx, p_h1,
                                             W2, b2, p_nd, Wout, p_yh, N);
    // 9: out = pull(yh) + bout
    pull_h16_kernel<2><<<pullGrid, TB>>>(p_yh, p_rowptr, p_colidx, nullptr, nullptr, bout, out, nullptr, N);
}

// round 13
// speedup vs baseline: 1.0498x; 1.0498x over previous
#include <cuda_runtime.h>
#include <cuda_bf16.h>
#include <cuda_fp16.h>
#include <cstdint>

#define NMAX 100000
#define EMAX 1600000

// ---------------- scratch (static device globals; no allocation) ----------------
__device__ int   g_degin [NMAX];
__device__ int   g_degout[NMAX];
__device__ float g_ns[NMAX];
__device__ float g_nd[NMAX];
__device__ int   g_rowptr[NMAX + 1];
__device__ int   g_cursor[NMAX];
__device__ int   g_bsum[256];
__device__ int   g_colidx[EMAX];
__device__ __align__(256) __half g_preh[NMAX * 64];   // fp16 pull payloads
__device__ __align__(256) __half g_h1nh[NMAX * 64];
__device__ __align__(256) __half g_yh  [NMAX * 64];
__device__ __align__(256) float  g_h1  [NMAX * 64];   // fp32 GEMM inputs
__device__ __align__(256) float  g_agg [NMAX * 64];

// pack two floats -> fp16x2 in a uint32
__device__ __forceinline__ uint32_t pack_h2(float a, float b) {
    uint32_t lo = (uint32_t)__half_as_ushort(__float2half_rn(a));
    uint32_t hi = (uint32_t)__half_as_ushort(__float2half_rn(b));
    return lo | (hi << 16);
}

// ---------------- small kernels ----------------

__global__ void zero_deg_kernel(int* __restrict__ a, int* __restrict__ b, int N) {
    int i = blockIdx.x * blockDim.x + threadIdx.x;
    if (i < N) { a[i] = 0; b[i] = 0; }
}

// 2 edges per thread via int2 loads
__global__ void degree_kernel(const int* __restrict__ src, const int* __restrict__ dst,
                              int* __restrict__ dout, int* __restrict__ din, int E) {
    int i = blockIdx.x * blockDim.x + threadIdx.x;
    int e0 = i * 2;
    if (e0 + 1 < E) {
        int2 s2 = *reinterpret_cast<const int2*>(src + e0);
        int2 d2 = *reinterpret_cast<const int2*>(dst + e0);
        atomicAdd(&dout[s2.x], 1);
        atomicAdd(&dout[s2.y], 1);
        atomicAdd(&din [d2.x], 1);
        atomicAdd(&din [d2.y], 1);
    } else if (e0 < E) {
        atomicAdd(&dout[src[e0]], 1);
        atomicAdd(&din [dst[e0]], 1);
    }
}

// block-level exclusive scan of deg_in -> rowptr partials + block sums; fused norm
__global__ void scan1_kernel(const int* __restrict__ degin, const int* __restrict__ degout,
                             int* __restrict__ rowptr, int* __restrict__ bsum,
                             float* __restrict__ ns, float* __restrict__ nd, int N) {
    __shared__ int s[512];
    int t = threadIdx.x;
    int i = blockIdx.x * 512 + t;
    int v = (i < N) ? degin[i] : 0;
    s[t] = v; __syncthreads();
    for (int off = 1; off < 512; off <<= 1) {
        int u = (t >= off) ? s[t - off] : 0;
        __syncthreads();
        s[t] += u;
        __syncthreads();
    }
    if (i < N) {
        rowptr[i] = s[t] - v;
        nd[i] = rsqrtf((float)max(v, 1));
        ns[i] = rsqrtf((float)max(degout[i], 1));
    }
    if (t == 511) bsum[blockIdx.x] = s[511];
}

// finalize rowptr: every block scans the (<=256) block sums locally, applies offset
__global__ void scan3_kernel(int* __restrict__ rowptr, int* __restrict__ cursor,
                             const int* __restrict__ bsum, int nb, int N, int E) {
    __shared__ int sb[256];
    int t = threadIdx.x;
    int v = (t < nb) ? bsum[t] : 0;
    sb[t] = v; __syncthreads();
    for (int off = 1; off < 256; off <<= 1) {
        int u = (t >= off) ? sb[t - off] : 0;
        __syncthreads();
        sb[t] += u;
        __syncthreads();
    }
    int ex = sb[t] - v;
    __syncthreads();
    sb[t] = ex;
    __syncthreads();
    int i = blockIdx.x * blockDim.x + threadIdx.x;
    if (i < N) {
        int r = rowptr[i] + sb[i >> 9];
        rowptr[i] = r;
        cursor[i] = r;
    }
    if (i == 0) rowptr[N] = E;
}

__global__ void csrfill_kernel(const int* __restrict__ src, const int* __restrict__ dst,
                               int* __restrict__ cursor, int* __restrict__ colidx, int E) {
    int e = blockIdx.x * blockDim.x + threadIdx.x;
    if (e >= E) return;
    int slot = atomicAdd(&cursor[dst[e]], 1);
    colidx[slot] = src[e];
}

// ================= split-bf16 mma.sync GEMM pieces (compute_100-legal) =================

__device__ __forceinline__ void mma_bf16(float* c, const uint32_t* a, const uint32_t* b) {
    asm volatile(
        "mma.sync.aligned.m16n8k16.row.col.f32.bf16.bf16.f32 "
        "{%0,%1,%2,%3}, {%4,%5,%6,%7}, {%8,%9}, {%0,%1,%2,%3};"
        : "+f"(c[0]), "+f"(c[1]), "+f"(c[2]), "+f"(c[3])
        : "r"(a[0]), "r"(a[1]), "r"(a[2]), "r"(a[3]), "r"(b[0]), "r"(b[1]));
}

__device__ __forceinline__ void cvt_pair(float f0, float f1, uint32_t& hi, uint32_t& lo) {
    __nv_bfloat16 h0 = __float2bfloat16(f0);
    __nv_bfloat16 h1 = __float2bfloat16(f1);
    __nv_bfloat16 l0 = __float2bfloat16(f0 - __bfloat162float(h0));
    __nv_bfloat16 l1 = __float2bfloat16(f1 - __bfloat162float(h1));
    hi = (uint32_t)__bfloat16_as_ushort(h0) | ((uint32_t)__bfloat16_as_ushort(h1) << 16);
    lo = (uint32_t)__bfloat16_as_ushort(l0) | ((uint32_t)__bfloat16_as_ushort(l1) << 16);
}

// layer-1 GEMM: preh[N,64] = fp16( (feats*ns)[N,128] @ W1[128,64] )
__global__ void __launch_bounds__(256)
gemm1_kernel(const float* __restrict__ A, const float* __restrict__ W,
             const float* __restrict__ ns, __half* __restrict__ outh, int N) {
    extern __shared__ uint32_t sm[];
    constexpr int K = 128, P = K / 2 + 4, K4 = K / 4;
    uint32_t* sAh = sm;
    uint32_t* sAl = sm + 128 * P;
    uint32_t* sBh = sm + 256 * P;
    uint32_t* sBl = sm + 256 * P + 64 * P;

    const int tid = threadIdx.x;
    const int wid = tid >> 5, lane = tid & 31;
    const int gid = lane >> 2, t = lane & 3;
    const int n0 = blockIdx.x * 128;

    for (int idx = tid; idx < 128 * K4; idx += 256) {
        int m = idx / K4, f = idx % K4;
        int node = n0 + m;
        float4 v = make_float4(0.f, 0.f, 0.f, 0.f);
        if (node < N) {
            v = reinterpret_cast<const float4*>(A + (size_t)node * K)[f];
            float s = ns[node];
            v.x *= s; v.y *= s; v.z *= s; v.w *= s;
        }
        uint32_t h0, l0, h1, l1;
        cvt_pair(v.x, v.y, h0, l0);
        cvt_pair(v.z, v.w, h1, l1);
        int o = m * P + f * 2;
        sAh[o] = h0; sAh[o + 1] = h1;
        sAl[o] = l0; sAl[o + 1] = l1;
    }
    for (int idx = tid; idx < 64 * (K / 2); idx += 256) {
        int n = idx & 63, kp = idx >> 6;
        uint32_t h, l;
        cvt_pair(W[(size_t)(2 * kp) * 64 + n], W[(size_t)(2 * kp + 1) * 64 + n], h, l);
        sBh[n * P + kp] = h; sBl[n * P + kp] = l;
    }
    __syncthreads();

    float acc[8][4];
#pragma unroll
    for (int nt = 0; nt < 8; nt++)
#pragma unroll
        for (int j = 0; j < 4; j++) acc[nt][j] = 0.f;

    const int r0 = wid * 16 + gid;
#pragma unroll
    for (int ks = 0; ks < K / 16; ks++) {
        int kb = ks * 8;
        uint32_t ah[4], al[4];
        ah[0] = sAh[ r0      * P + kb + t];
        ah[1] = sAh[(r0 + 8) * P + kb + t];
        ah[2] = sAh[ r0      * P + kb + 4 + t];
        ah[3] = sAh[(r0 + 8) * P + kb + 4 + t];
        al[0] = sAl[ r0      * P + kb + t];
        al[1] = sAl[(r0 + 8) * P + kb + t];
        al[2] = sAl[ r0      * P + kb + 4 + t];
        al[3] = sAl[(r0 + 8) * P + kb + 4 + t];
#pragma unroll
        for (int nt = 0; nt < 8; nt++) {
            int n = nt * 8 + gid;
            uint32_t bh[2], bl[2];
            bh[0] = sBh[n * P + kb + t];
            bh[1] = sBh[n * P + kb + 4 + t];
            bl[0] = sBl[n * P + kb + t];
            bl[1] = sBl[n * P + kb + 4 + t];
            mma_bf16(acc[nt], ah, bh);
            mma_bf16(acc[nt], ah, bl);
            mma_bf16(acc[nt], al, bh);
        }
    }

    const int node0 = n0 + r0, node1 = node0 + 8;
#pragma unroll
    for (int nt = 0; nt < 8; nt++) {
        int col = nt * 8 + t * 2;
        if (node0 < N)
            *reinterpret_cast<uint32_t*>(outh + (size_t)node0 * 64 + col) = pack_h2(acc[nt][0], acc[nt][1]);
        if (node1 < N)
            *reinterpret_cast<uint32_t*>(outh + (size_t)node1 * 64 + col) = pack_h2(acc[nt][2], acc[nt][3]);
    }
}

// fused layers 2+3: h2 = relu((agg@W2)*nd + b2) [kept in regs];
//                   yh = fp16( [h1|h2] @ Wout )
__global__ void __launch_bounds__(256)
gemm23_kernel(const float* __restrict__ agg, const float* __restrict__ h1,
              const float* __restrict__ W2, const float* __restrict__ b2,
              const float* __restrict__ nd, const float* __restrict__ Wout,
              __half* __restrict__ yh, int N) {
    extern __shared__ uint32_t sm[];
    constexpr int P1 = 64 / 2 + 4;    // 36
    constexpr int P2 = 128 / 2 + 4;   // 68

    const int tid = threadIdx.x;
    const int wid = tid >> 5, lane = tid & 31;
    const int gid = lane >> 2, t = lane & 3;
    const int n0 = blockIdx.x * 128;
    const int r0 = wid * 16 + gid;
    const int node0 = n0 + r0, node1 = node0 + 8;

    // ---------- phase 1: acc = agg @ W2  (K=64) ----------
    {
        uint32_t* sAh = sm;
        uint32_t* sAl = sm + 128 * P1;
        uint32_t* sBh = sm + 256 * P1;
        uint32_t* sBl = sm + 256 * P1 + 64 * P1;

        for (int idx = tid; idx < 128 * 16; idx += 256) {
            int m = idx / 16, f = idx % 16;
            int node = n0 + m;
            float4 v = make_float4(0.f, 0.f, 0.f, 0.f);
            if (node < N) v = reinterpret_cast<const float4*>(agg + (size_t)node * 64)[f];
            uint32_t h0, l0, h1v, l1;
            cvt_pair(v.x, v.y, h0, l0);
            cvt_pair(v.z, v.w, h1v, l1);
            int o = m * P1 + f * 2;
            sAh[o] = h0; sAh[o + 1] = h1v;
            sAl[o] = l0; sAl[o + 1] = l1;
        }
        for (int idx = tid; idx < 64 * 32; idx += 256) {
            int n = idx & 63, kp = idx >> 6;
            uint32_t h, l;
            cvt_pair(W2[(size_t)(2 * kp) * 64 + n], W2[(size_t)(2 * kp + 1) * 64 + n], h, l);
            sBh[n * P1 + kp] = h; sBl[n * P1 + kp] = l;
        }
        __syncthreads();

        float acc[8][4];
#pragma unroll
        for (int nt = 0; nt < 8; nt++)
#pragma unroll
            for (int j = 0; j < 4; j++) acc[nt][j] = 0.f;

#pragma unroll
        for (int ks = 0; ks < 4; ks++) {
            int kb = ks * 8;
            uint32_t ah[4], al[4];
            ah[0] = sAh[ r0      * P1 + kb + t];
            ah[1] = sAh[(r0 + 8) * P1 + kb + t];
            ah[2] = sAh[ r0      * P1 + kb + 4 + t];
            ah[3] = sAh[(r0 + 8) * P1 + kb + 4 + t];
            al[0] = sAl[ r0      * P1 + kb + t];
            al[1] = sAl[(r0 + 8) * P1 + kb + t];
            al[2] = sAl[ r0      * P1 + kb + 4 + t];
            al[3] = sAl[(r0 + 8) * P1 + kb + 4 + t];
#pragma unroll
            for (int nt = 0; nt < 8; nt++) {
                int n = nt * 8 + gid;
                uint32_t bh[2], bl[2];
                bh[0] = sBh[n * P1 + kb + t];
                bh[1] = sBh[n * P1 + kb + 4 + t];
                bl[0] = sBl[n * P1 + kb + t];
                bl[1] = sBl[n * P1 + kb + 4 + t];
                mma_bf16(acc[nt], ah, bh);
                mma_bf16(acc[nt], ah, bl);
                mma_bf16(acc[nt], al, bh);
            }
        }

        // epilogue: h2 = relu(acc*nd + b2), restage into phase-2 A (k = 64+col)
        float d0 = (node0 < N) ? nd[node0] : 0.f;
        float d1 = (node1 < N) ? nd[node1] : 0.f;
        float h2v[8][4];
#pragma unroll
        for (int nt = 0; nt < 8; nt++) {
            int col = nt * 8 + t * 2;
            float2 bb = *reinterpret_cast<const float2*>(b2 + col);
            h2v[nt][0] = fmaxf(fmaf(acc[nt][0], d0, bb.x), 0.f);
            h2v[nt][1] = fmaxf(fmaf(acc[nt][1], d0, bb.y), 0.f);
            h2v[nt][2] = fmaxf(fmaf(acc[nt][2], d1, bb.x), 0.f);
            h2v[nt][3] = fmaxf(fmaf(acc[nt][3], d1, bb.y), 0.f);
        }
        __syncthreads();   // phase-1 smem reads done; safe to overwrite

        // ---------- phase 2 staging ----------
        uint32_t* sAh2 = sm;
        uint32_t* sAl2 = sm + 128 * P2;
        uint32_t* sBh2 = sm + 256 * P2;
        uint32_t* sBl2 = sm + 256 * P2 + 64 * P2;

        // h1 part (k 0..63)
        for (int idx = tid; idx < 128 * 16; idx += 256) {
            int m = idx / 16, f = idx % 16;
            int node = n0 + m;
            float4 v = make_float4(0.f, 0.f, 0.f, 0.f);
            if (node < N) v = reinterpret_cast<const float4*>(h1 + (size_t)node * 64)[f];
            uint32_t h0, l0, h1v, l1;
            cvt_pair(v.x, v.y, h0, l0);
            cvt_pair(v.z, v.w, h1v, l1);
            int o = m * P2 + f * 2;
            sAh2[o] = h0; sAh2[o + 1] = h1v;
            sAl2[o] = l0; sAl2[o + 1] = l1;
        }
        // h2 part from registers (k 64..127 -> kp 32..63)
#pragma unroll
        for (int nt = 0; nt < 8; nt++) {
            int kp = 32 + nt * 4 + t;
            uint32_t h, l;
            cvt_pair(h2v[nt][0], h2v[nt][1], h, l);
            sAh2[r0 * P2 + kp] = h; sAl2[r0 * P2 + kp] = l;
            cvt_pair(h2v[nt][2], h2v[nt][3], h, l);
            sAh2[(r0 + 8) * P2 + kp] = h; sAl2[(r0 + 8) * P2 + kp] = l;
        }
        // B = Wout^T (K=128)
        for (int idx = tid; idx < 64 * 64; idx += 256) {
            int n = idx & 63, kp = idx >> 6;
            uint32_t h, l;
            cvt_pair(Wout[(size_t)(2 * kp) * 64 + n], Wout[(size_t)(2 * kp + 1) * 64 + n], h, l);
            sBh2[n * P2 + kp] = h; sBl2[n * P2 + kp] = l;
        }
        __syncthreads();

        // ---------- phase 2 MMA: y = [h1|h2] @ Wout ----------
#pragma unroll
        for (int nt = 0; nt < 8; nt++)
#pragma unroll
            for (int j = 0; j < 4; j++) acc[nt][j] = 0.f;

#pragma unroll
        for (int ks = 0; ks < 8; ks++) {
            int kb = ks * 8;
            uint32_t ah[4], al[4];
            ah[0] = sAh2[ r0      * P2 + kb + t];
            ah[1] = sAh2[(r0 + 8) * P2 + kb + t];
            ah[2] = sAh2[ r0      * P2 + kb + 4 + t];
            ah[3] = sAh2[(r0 + 8) * P2 + kb + 4 + t];
            al[0] = sAl2[ r0      * P2 + kb + t];
            al[1] = sAl2[(r0 + 8) * P2 + kb + t];
            al[2] = sAl2[ r0      * P2 + kb + 4 + t];
            al[3] = sAl2[(r0 + 8) * P2 + kb + 4 + t];
#pragma unroll
            for (int nt = 0; nt < 8; nt++) {
                int n = nt * 8 + gid;
                uint32_t bh[2], bl[2];
                bh[0] = sBh2[n * P2 + kb + t];
                bh[1] = sBh2[n * P2 + kb + 4 + t];
                bl[0] = sBl2[n * P2 + kb + t];
                bl[1] = sBl2[n * P2 + kb + 4 + t];
                mma_bf16(acc[nt], ah, bh);
                mma_bf16(acc[nt], ah, bl);
                mma_bf16(acc[nt], al, bh);
            }
        }

#pragma unroll
        for (int nt = 0; nt < 8; nt++) {
            int col = nt * 8 + t * 2;
            if (node0 < N)
                *reinterpret_cast<uint32_t*>(yh + (size_t)node0 * 64 + col) = pack_h2(acc[nt][0], acc[nt][1]);
            if (node1 < N)
                *reinterpret_cast<uint32_t*>(yh + (size_t)node1 * 64 + col) = pack_h2(acc[nt][2], acc[nt][3]);
        }
    }
}

// ---------------- fp16-payload pull: one warp/node, quarter-warp per edge row ----------------
// EPI: 0 = fp32 store to o1 (agg)
//      1 = h = relu(acc*nd + b); o1 = h (fp32); o2 = (h*ns) fp16 payload
//      2 = o1 = acc + b (fp32 output)
template<int EPI>
__global__ void __launch_bounds__(256)
pull_h16_kernel(const __half* __restrict__ tab,
                const int* __restrict__ rowptr, const int* __restrict__ colidx,
                const float* __restrict__ ns, const float* __restrict__ nd,
                const float* __restrict__ b,
                float* __restrict__ o1, __half* __restrict__ o2, int N) {
    int node = (blockIdx.x * blockDim.x + threadIdx.x) >> 5;
    if (node >= N) return;
    const int lane = threadIdx.x & 31;
    const int grp = lane >> 3;
    const int q   = lane & 7;
    const int beg = __ldg(&rowptr[node]);
    const int deg = __ldg(&rowptr[node + 1]) - beg;

    float acc[8];
#pragma unroll
    for (int j = 0; j < 8; j++) acc[j] = 0.f;

    int i = 0;
    int chunk = (deg < 32) ? deg : 32;
    int my = (deg > 0) ? __ldg(&colidx[beg + ((lane < chunk) ? lane : 0)]) : 0;
    while (i < deg) {
        int nq = (chunk + 3) >> 2;
        int cur_my = my, cur_chunk = chunk;
        int ni = i + chunk;
        if (ni < deg) {                     // prefetch next chunk's indices
            int rem = deg - ni;
            chunk = (rem < 32) ? rem : 32;
            my = __ldg(&colidx[beg + ni + ((lane < chunk) ? lane : 0)]);
        }
#pragma unroll 4
        for (int p = 0; p < nq; p++) {
            int j = 4 * p + grp;
            bool act = (j < cur_chunk);
            int s = __shfl_sync(0xffffffffu, cur_my, act ? j : 0);
            uint4 v = *reinterpret_cast<const uint4*>(tab + (size_t)s * 64 + q * 8);
            if (act) {
                const __half2* hp = reinterpret_cast<const __half2*>(&v);
                float2 f0 = __half22float2(hp[0]);
                float2 f1 = __half22float2(hp[1]);
                float2 f2 = __half22float2(hp[2]);
                float2 f3 = __half22float2(hp[3]);
                acc[0] += f0.x; acc[1] += f0.y;
                acc[2] += f1.x; acc[3] += f1.y;
                acc[4] += f2.x; acc[5] += f2.y;
                acc[6] += f3.x; acc[7] += f3.y;
            }
        }
        i = ni;
    }

#pragma unroll
    for (int j = 0; j < 8; j++) {
        acc[j] += __shfl_xor_sync(0xffffffffu, acc[j], 8);
        acc[j] += __shfl_xor_sync(0xffffffffu, acc[j], 16);
    }
    if (grp != 0) return;

    float* o1p = o1 + (size_t)node * 64 + q * 8;
    if (EPI == 0) {
        reinterpret_cast<float4*>(o1p)[0] = make_float4(acc[0], acc[1], acc[2], acc[3]);
        reinterpret_cast<float4*>(o1p)[1] = make_float4(acc[4], acc[5], acc[6], acc[7]);
    } else if (EPI == 1) {
        float d = nd[node];
        float4 b0 = reinterpret_cast<const float4*>(b + q * 8)[0];
        float4 b1 = reinterpret_cast<const float4*>(b + q * 8)[1];
        float h[8];
        h[0] = fmaxf(fmaf(acc[0], d, b0.x), 0.f);
        h[1] = fmaxf(fmaf(acc[1], d, b0.y), 0.f);
        h[2] = fmaxf(fmaf(acc[2], d, b0.z), 0.f);
        h[3] = fmaxf(fmaf(acc[3], d, b0.w), 0.f);
        h[4] = fmaxf(fmaf(acc[4], d, b1.x), 0.f);
        h[5] = fmaxf(fmaf(acc[5], d, b1.y), 0.f);
        h[6] = fmaxf(fmaf(acc[6], d, b1.z), 0.f);
        h[7] = fmaxf(fmaf(acc[7], d, b1.w), 0.f);
        reinterpret_cast<float4*>(o1p)[0] = make_float4(h[0], h[1], h[2], h[3]);
        reinterpret_cast<float4*>(o1p)[1] = make_float4(h[4], h[5], h[6], h[7]);
        float sn = ns[node];
        uint4 pk;
        pk.x = pack_h2(h[0] * sn, h[1] * sn);
        pk.y = pack_h2(h[2] * sn, h[3] * sn);
        pk.z = pack_h2(h[4] * sn, h[5] * sn);
        pk.w = pack_h2(h[6] * sn, h[7] * sn);
        *reinterpret_cast<uint4*>(o2 + (size_t)node * 64 + q * 8) = pk;
    } else {
        float4 b0 = reinterpret_cast<const float4*>(b + q * 8)[0];
        float4 b1 = reinterpret_cast<const float4*>(b + q * 8)[1];
        reinterpret_cast<float4*>(o1p)[0] =
            make_float4(acc[0] + b0.x, acc[1] + b0.y, acc[2] + b0.z, acc[3] + b0.w);
        reinterpret_cast<float4*>(o1p)[1] =
            make_float4(acc[4] + b1.x, acc[5] + b1.y, acc[6] + b1.z, acc[7] + b1.w);
    }
}

// ---------------- launch ----------------

extern "C" void kernel_launch(void* const* d_in, const int* in_sizes, int n_in,
                              void* d_out, int out_size) {
    const float* feats = (const float*)d_in[0];
    const int*   src   = (const int*)  d_in[1];
    const int*   dst   = (const int*)  d_in[2];
    const float* W1    = (const float*)d_in[3];
    const float* b1    = (const float*)d_in[4];
    const float* W2    = (const float*)d_in[5];
    const float* b2    = (const float*)d_in[6];
    const float* Wout  = (const float*)d_in[7];
    const float* bout  = (const float*)d_in[8];
    float* out = (float*)d_out;

    const int N = in_sizes[0] / 128;
    const int E = in_sizes[1];

    int *p_degin, *p_degout, *p_rowptr, *p_cursor, *p_bsum, *p_colidx;
    float *p_ns, *p_nd, *p_h1, *p_agg;
    __half *p_preh, *p_h1nh, *p_yh;
    cudaGetSymbolAddress((void**)&p_degin,  g_degin);
    cudaGetSymbolAddress((void**)&p_degout, g_degout);
    cudaGetSymbolAddress((void**)&p_rowptr, g_rowptr);
    cudaGetSymbolAddress((void**)&p_cursor, g_cursor);
    cudaGetSymbolAddress((void**)&p_bsum,   g_bsum);
    cudaGetSymbolAddress((void**)&p_colidx, g_colidx);
    cudaGetSymbolAddress((void**)&p_ns,     g_ns);
    cudaGetSymbolAddress((void**)&p_nd,     g_nd);
    cudaGetSymbolAddress((void**)&p_preh,   g_preh);
    cudaGetSymbolAddress((void**)&p_h1nh,   g_h1nh);
    cudaGetSymbolAddress((void**)&p_yh,     g_yh);
    cudaGetSymbolAddress((void**)&p_h1,     g_h1);
    cudaGetSymbolAddress((void**)&p_agg,    g_agg);

    const int TB = 256;
    auto cdiv = [](long long a, long long b) { return (unsigned)((a + b - 1) / b); };
    const int nb = (int)cdiv(N, 512);        // <= 256 for N <= 131072

    const int SMEM_BIG = 384 * (128 / 2 + 4) * 4;   // 104448
    cudaFuncSetAttribute(gemm1_kernel,  cudaFuncAttributeMaxDynamicSharedMemorySize, SMEM_BIG);
    cudaFuncSetAttribute(gemm23_kernel, cudaFuncAttributeMaxDynamicSharedMemorySize, SMEM_BIG);

    // 1-5: degrees, norms, CSR
    zero_deg_kernel<<<cdiv(N, TB), TB>>>(p_degin, p_degout, N);
    degree_kernel  <<<cdiv(cdiv(E, 2), TB), TB>>>(src, dst, p_degout, p_degin, E);
    scan1_kernel   <<<nb, 512>>>(p_degin, p_degout, p_rowptr, p_bsum, p_ns, p_nd, N);
    scan3_kernel   <<<cdiv(N, TB), TB>>>(p_rowptr, p_cursor, p_bsum, nb, N, E);
    csrfill_kernel <<<cdiv(E, TB), TB>>>(src, dst, p_cursor, p_colidx, E);

    const unsigned mmaGrid  = cdiv(N, 128);
    const unsigned pullGrid = cdiv((long long)N * 32, TB);

    // 6: preh = (feats*ns)@W1 (fp16)
    gemm1_kernel<<<mmaGrid, TB, SMEM_BIG>>>(feats, W1, p_ns, p_preh, N);
    // 7: h1 = relu(pull(preh)*nd + b1); h1nh = (h1*ns) fp16
    pull_h16_kernel<1><<<pullGrid, TB>>>(p_preh, p_rowptr, p_colidx, p_ns, p_nd, b1, p_h1, p_h1nh, N);
    // 8: agg = pull(h1nh)
    pull_h16_kernel<0><<<pullGrid, TB>>>(p_h1nh, p_rowptr, p_colidx, nullptr, nullptr, nullptr, p_agg, nullptr, N);
    // 9: h2 = relu((agg@W2)*nd+b2) [regs]; yh = [h1|h2]@Wout (fp16)
    gemm23_kernel<<<mmaGrid, TB, SMEM_BIG>>>(p_agg, p_h1, W2, b2, p_nd, Wout, p_yh, N);
    // 10: out = pull(yh) + bout
    pull_h16_kernel<2><<<pullGrid, TB>>>(p_yh, p_rowptr, p_colidx, nullptr, nullptr, bout, out, nullptr, N);
}

// round 14
// speedup vs baseline: 1.0969x; 1.0449x over previous
#include <cuda_runtime.h>
#include <cuda_bf16.h>
#include <cuda_fp16.h>
#include <cstdint>

#define NMAX 100000
#define EMAX 1600000

// ---------------- scratch (static device globals; no allocation) ----------------
__device__ int   g_degin [NMAX];
__device__ int   g_degout[NMAX];
__device__ float g_ns[NMAX];
__device__ float g_nd[NMAX];
__device__ int   g_rowptr[NMAX + 1];
__device__ int   g_cursor[NMAX];
__device__ int   g_bsum[256];
__device__ int   g_colidx[EMAX];
__device__ __align__(256) __half g_preh[NMAX * 64];   // fp16 pull payloads
__device__ __align__(256) __half g_h1nh[NMAX * 64];
__device__ __align__(256) __half g_yh  [NMAX * 64];
__device__ __align__(256) float  g_h1  [NMAX * 64];   // fp32 GEMM inputs
__device__ __align__(256) float  g_agg [NMAX * 64];

// pack two floats -> fp16x2 in a uint32
__device__ __forceinline__ uint32_t pack_h2(float a, float b) {
    uint32_t lo = (uint32_t)__half_as_ushort(__float2half_rn(a));
    uint32_t hi = (uint32_t)__half_as_ushort(__float2half_rn(b));
    return lo | (hi << 16);
}

// ---------------- small kernels ----------------

__global__ void zero_deg_kernel(int* __restrict__ a, int* __restrict__ b, int N) {
    int i = blockIdx.x * blockDim.x + threadIdx.x;
    if (i < N) { a[i] = 0; b[i] = 0; }
}

// 2 edges per thread via int2 loads
__global__ void degree_kernel(const int* __restrict__ src, const int* __restrict__ dst,
                              int* __restrict__ dout, int* __restrict__ din, int E) {
    int i = blockIdx.x * blockDim.x + threadIdx.x;
    int e0 = i * 2;
    if (e0 + 1 < E) {
        int2 s2 = *reinterpret_cast<const int2*>(src + e0);
        int2 d2 = *reinterpret_cast<const int2*>(dst + e0);
        atomicAdd(&dout[s2.x], 1);
        atomicAdd(&dout[s2.y], 1);
        atomicAdd(&din [d2.x], 1);
        atomicAdd(&din [d2.y], 1);
    } else if (e0 < E) {
        atomicAdd(&dout[src[e0]], 1);
        atomicAdd(&din [dst[e0]], 1);
    }
}

// block-level exclusive scan of deg_in -> rowptr partials + block sums; fused norm
__global__ void scan1_kernel(const int* __restrict__ degin, const int* __restrict__ degout,
                             int* __restrict__ rowptr, int* __restrict__ bsum,
                             float* __restrict__ ns, float* __restrict__ nd, int N) {
    __shared__ int s[512];
    int t = threadIdx.x;
    int i = blockIdx.x * 512 + t;
    int v = (i < N) ? degin[i] : 0;
    s[t] = v; __syncthreads();
    for (int off = 1; off < 512; off <<= 1) {
        int u = (t >= off) ? s[t - off] : 0;
        __syncthreads();
        s[t] += u;
        __syncthreads();
    }
    if (i < N) {
        rowptr[i] = s[t] - v;
        nd[i] = rsqrtf((float)max(v, 1));
        ns[i] = rsqrtf((float)max(degout[i], 1));
    }
    if (t == 511) bsum[blockIdx.x] = s[511];
}

// finalize rowptr: every block scans the (<=256) block sums locally, applies offset
__global__ void scan3_kernel(int* __restrict__ rowptr, int* __restrict__ cursor,
                             const int* __restrict__ bsum, int nb, int N, int E) {
    __shared__ int sb[256];
    int t = threadIdx.x;
    int v = (t < nb) ? bsum[t] : 0;
    sb[t] = v; __syncthreads();
    for (int off = 1; off < 256; off <<= 1) {
        int u = (t >= off) ? sb[t - off] : 0;
        __syncthreads();
        sb[t] += u;
        __syncthreads();
    }
    int ex = sb[t] - v;
    __syncthreads();
    sb[t] = ex;
    __syncthreads();
    int i = blockIdx.x * blockDim.x + threadIdx.x;
    if (i < N) {
        int r = rowptr[i] + sb[i >> 9];
        rowptr[i] = r;
        cursor[i] = r;
    }
    if (i == 0) rowptr[N] = E;
}

// 2 edges per thread via int2 loads
__global__ void csrfill_kernel(const int* __restrict__ src, const int* __restrict__ dst,
                               int* __restrict__ cursor, int* __restrict__ colidx, int E) {
    int i = blockIdx.x * blockDim.x + threadIdx.x;
    int e0 = i * 2;
    if (e0 + 1 < E) {
        int2 s2 = *reinterpret_cast<const int2*>(src + e0);
        int2 d2 = *reinterpret_cast<const int2*>(dst + e0);
        int slot0 = atomicAdd(&cursor[d2.x], 1);
        colidx[slot0] = s2.x;
        int slot1 = atomicAdd(&cursor[d2.y], 1);
        colidx[slot1] = s2.y;
    } else if (e0 < E) {
        int slot = atomicAdd(&cursor[dst[e0]], 1);
        colidx[slot] = src[e0];
    }
}

// ================= split-bf16 mma.sync GEMM pieces (compute_100-legal) =================

__device__ __forceinline__ void mma_bf16(float* c, const uint32_t* a, const uint32_t* b) {
    asm volatile(
        "mma.sync.aligned.m16n8k16.row.col.f32.bf16.bf16.f32 "
        "{%0,%1,%2,%3}, {%4,%5,%6,%7}, {%8,%9}, {%0,%1,%2,%3};"
        : "+f"(c[0]), "+f"(c[1]), "+f"(c[2]), "+f"(c[3])
        : "r"(a[0]), "r"(a[1]), "r"(a[2]), "r"(a[3]), "r"(b[0]), "r"(b[1]));
}

__device__ __forceinline__ void cvt_pair(float f0, float f1, uint32_t& hi, uint32_t& lo) {
    __nv_bfloat16 h0 = __float2bfloat16(f0);
    __nv_bfloat16 h1 = __float2bfloat16(f1);
    __nv_bfloat16 l0 = __float2bfloat16(f0 - __bfloat162float(h0));
    __nv_bfloat16 l1 = __float2bfloat16(f1 - __bfloat162float(h1));
    hi = (uint32_t)__bfloat16_as_ushort(h0) | ((uint32_t)__bfloat16_as_ushort(h1) << 16);
    lo = (uint32_t)__bfloat16_as_ushort(l0) | ((uint32_t)__bfloat16_as_ushort(l1) << 16);
}

// layer-1 GEMM: preh[N,64] = fp16( (feats*ns)[N,128] @ W1[128,64] )
__global__ void __launch_bounds__(256)
gemm1_kernel(const float* __restrict__ A, const float* __restrict__ W,
             const float* __restrict__ ns, __half* __restrict__ outh, int N) {
    extern __shared__ uint32_t sm[];
    constexpr int K = 128, P = K / 2 + 4, K4 = K / 4;
    uint32_t* sAh = sm;
    uint32_t* sAl = sm + 128 * P;
    uint32_t* sBh = sm + 256 * P;
    uint32_t* sBl = sm + 256 * P + 64 * P;

    const int tid = threadIdx.x;
    const int wid = tid >> 5, lane = tid & 31;
    const int gid = lane >> 2, t = lane & 3;
    const int n0 = blockIdx.x * 128;

    for (int idx = tid; idx < 128 * K4; idx += 256) {
        int m = idx / K4, f = idx % K4;
        int node = n0 + m;
        float4 v = make_float4(0.f, 0.f, 0.f, 0.f);
        if (node < N) {
            v = reinterpret_cast<const float4*>(A + (size_t)node * K)[f];
            float s = ns[node];
            v.x *= s; v.y *= s; v.z *= s; v.w *= s;
        }
        uint32_t h0, l0, h1, l1;
        cvt_pair(v.x, v.y, h0, l0);
        cvt_pair(v.z, v.w, h1, l1);
        int o = m * P + f * 2;
        sAh[o] = h0; sAh[o + 1] = h1;
        sAl[o] = l0; sAl[o + 1] = l1;
    }
    for (int idx = tid; idx < 64 * (K / 2); idx += 256) {
        int n = idx & 63, kp = idx >> 6;
        uint32_t h, l;
        cvt_pair(W[(size_t)(2 * kp) * 64 + n], W[(size_t)(2 * kp + 1) * 64 + n], h, l);
        sBh[n * P + kp] = h; sBl[n * P + kp] = l;
    }
    __syncthreads();

    float acc[8][4];
#pragma unroll
    for (int nt = 0; nt < 8; nt++)
#pragma unroll
        for (int j = 0; j < 4; j++) acc[nt][j] = 0.f;

    const int r0 = wid * 16 + gid;
#pragma unroll
    for (int ks = 0; ks < K / 16; ks++) {
        int kb = ks * 8;
        uint32_t ah[4], al[4];
        ah[0] = sAh[ r0      * P + kb + t];
        ah[1] = sAh[(r0 + 8) * P + kb + t];
        ah[2] = sAh[ r0      * P + kb + 4 + t];
        ah[3] = sAh[(r0 + 8) * P + kb + 4 + t];
        al[0] = sAl[ r0      * P + kb + t];
        al[1] = sAl[(r0 + 8) * P + kb + t];
        al[2] = sAl[ r0      * P + kb + 4 + t];
        al[3] = sAl[(r0 + 8) * P + kb + 4 + t];
#pragma unroll
        for (int nt = 0; nt < 8; nt++) {
            int n = nt * 8 + gid;
            uint32_t bh[2], bl[2];
            bh[0] = sBh[n * P + kb + t];
            bh[1] = sBh[n * P + kb + 4 + t];
            bl[0] = sBl[n * P + kb + t];
            bl[1] = sBl[n * P + kb + 4 + t];
            mma_bf16(acc[nt], ah, bh);
            mma_bf16(acc[nt], ah, bl);
            mma_bf16(acc[nt], al, bh);
        }
    }

    const int node0 = n0 + r0, node1 = node0 + 8;
#pragma unroll
    for (int nt = 0; nt < 8; nt++) {
        int col = nt * 8 + t * 2;
        if (node0 < N)
            *reinterpret_cast<uint32_t*>(outh + (size_t)node0 * 64 + col) = pack_h2(acc[nt][0], acc[nt][1]);
        if (node1 < N)
            *reinterpret_cast<uint32_t*>(outh + (size_t)node1 * 64 + col) = pack_h2(acc[nt][2], acc[nt][3]);
    }
}

// fused layers 2+3: h2 = relu((agg@W2)*nd + b2) [kept in regs];
//                   yh = fp16( [h1|h2] @ Wout )
__global__ void __launch_bounds__(256)
gemm23_kernel(const float* __restrict__ agg, const float* __restrict__ h1,
              const float* __restrict__ W2, const float* __restrict__ b2,
              const float* __restrict__ nd, const float* __restrict__ Wout,
              __half* __restrict__ yh, int N) {
    extern __shared__ uint32_t sm[];
    constexpr int P1 = 64 / 2 + 4;    // 36
    constexpr int P2 = 128 / 2 + 4;   // 68

    const int tid = threadIdx.x;
    const int wid = tid >> 5, lane = tid & 31;
    const int gid = lane >> 2, t = lane & 3;
    const int n0 = blockIdx.x * 128;
    const int r0 = wid * 16 + gid;
    const int node0 = n0 + r0, node1 = node0 + 8;

    // ---------- phase 1: acc = agg @ W2  (K=64) ----------
    {
        uint32_t* sAh = sm;
        uint32_t* sAl = sm + 128 * P1;
        uint32_t* sBh = sm + 256 * P1;
        uint32_t* sBl = sm + 256 * P1 + 64 * P1;

        for (int idx = tid; idx < 128 * 16; idx += 256) {
            int m = idx / 16, f = idx % 16;
            int node = n0 + m;
            float4 v = make_float4(0.f, 0.f, 0.f, 0.f);
            if (node < N) v = reinterpret_cast<const float4*>(agg + (size_t)node * 64)[f];
            uint32_t h0, l0, h1v, l1;
            cvt_pair(v.x, v.y, h0, l0);
            cvt_pair(v.z, v.w, h1v, l1);
            int o = m * P1 + f * 2;
            sAh[o] = h0; sAh[o + 1] = h1v;
            sAl[o] = l0; sAl[o + 1] = l1;
        }
        for (int idx = tid; idx < 64 * 32; idx += 256) {
            int n = idx & 63, kp = idx >> 6;
            uint32_t h, l;
            cvt_pair(W2[(size_t)(2 * kp) * 64 + n], W2[(size_t)(2 * kp + 1) * 64 + n], h, l);
            sBh[n * P1 + kp] = h; sBl[n * P1 + kp] = l;
        }
        __syncthreads();

        float acc[8][4];
#pragma unroll
        for (int nt = 0; nt < 8; nt++)
#pragma unroll
            for (int j = 0; j < 4; j++) acc[nt][j] = 0.f;

#pragma unroll
        for (int ks = 0; ks < 4; ks++) {
            int kb = ks * 8;
            uint32_t ah[4], al[4];
            ah[0] = sAh[ r0      * P1 + kb + t];
            ah[1] = sAh[(r0 + 8) * P1 + kb + t];
            ah[2] = sAh[ r0      * P1 + kb + 4 + t];
            ah[3] = sAh[(r0 + 8) * P1 + kb + 4 + t];
            al[0] = sAl[ r0      * P1 + kb + t];
            al[1] = sAl[(r0 + 8) * P1 + kb + t];
            al[2] = sAl[ r0      * P1 + kb + 4 + t];
            al[3] = sAl[(r0 + 8) * P1 + kb + 4 + t];
#pragma unroll
            for (int nt = 0; nt < 8; nt++) {
                int n = nt * 8 + gid;
                uint32_t bh[2], bl[2];
                bh[0] = sBh[n * P1 + kb + t];
                bh[1] = sBh[n * P1 + kb + 4 + t];
                bl[0] = sBl[n * P1 + kb + t];
                bl[1] = sBl[n * P1 + kb + 4 + t];
                mma_bf16(acc[nt], ah, bh);
                mma_bf16(acc[nt], ah, bl);
                mma_bf16(acc[nt], al, bh);
            }
        }

        // epilogue: h2 = relu(acc*nd + b2), restage into phase-2 A (k = 64+col)
        float d0 = (node0 < N) ? nd[node0] : 0.f;
        float d1 = (node1 < N) ? nd[node1] : 0.f;
        float h2v[8][4];
#pragma unroll
        for (int nt = 0; nt < 8; nt++) {
            int col = nt * 8 + t * 2;
            float2 bb = *reinterpret_cast<const float2*>(b2 + col);
            h2v[nt][0] = fmaxf(fmaf(acc[nt][0], d0, bb.x), 0.f);
            h2v[nt][1] = fmaxf(fmaf(acc[nt][1], d0, bb.y), 0.f);
            h2v[nt][2] = fmaxf(fmaf(acc[nt][2], d1, bb.x), 0.f);
            h2v[nt][3] = fmaxf(fmaf(acc[nt][3], d1, bb.y), 0.f);
        }
        __syncthreads();   // phase-1 smem reads done; safe to overwrite

        // ---------- phase 2 staging ----------
        uint32_t* sAh2 = sm;
        uint32_t* sAl2 = sm + 128 * P2;
        uint32_t* sBh2 = sm + 256 * P2;
        uint32_t* sBl2 = sm + 256 * P2 + 64 * P2;

        // h1 part (k 0..63)
        for (int idx = tid; idx < 128 * 16; idx += 256) {
            int m = idx / 16, f = idx % 16;
            int node = n0 + m;
            float4 v = make_float4(0.f, 0.f, 0.f, 0.f);
            if (node < N) v = reinterpret_cast<const float4*>(h1 + (size_t)node * 64)[f];
            uint32_t h0, l0, h1v, l1;
            cvt_pair(v.x, v.y, h0, l0);
            cvt_pair(v.z, v.w, h1v, l1);
            int o = m * P2 + f * 2;
            sAh2[o] = h0; sAh2[o + 1] = h1v;
            sAl2[o] = l0; sAl2[o + 1] = l1;
        }
        // h2 part from registers (k 64..127 -> kp 32..63)
#pragma unroll
        for (int nt = 0; nt < 8; nt++) {
            int kp = 32 + nt * 4 + t;
            uint32_t h, l;
            cvt_pair(h2v[nt][0], h2v[nt][1], h, l);
            sAh2[r0 * P2 + kp] = h; sAl2[r0 * P2 + kp] = l;
            cvt_pair(h2v[nt][2], h2v[nt][3], h, l);
            sAh2[(r0 + 8) * P2 + kp] = h; sAl2[(r0 + 8) * P2 + kp] = l;
        }
        // B = Wout^T (K=128)
        for (int idx = tid; idx < 64 * 64; idx += 256) {
            int n = idx & 63, kp = idx >> 6;
            uint32_t h, l;
            cvt_pair(Wout[(size_t)(2 * kp) * 64 + n], Wout[(size_t)(2 * kp + 1) * 64 + n], h, l);
            sBh2[n * P2 + kp] = h; sBl2[n * P2 + kp] = l;
        }
        __syncthreads();

        // ---------- phase 2 MMA: y = [h1|h2] @ Wout ----------
#pragma unroll
        for (int nt = 0; nt < 8; nt++)
#pragma unroll
            for (int j = 0; j < 4; j++) acc[nt][j] = 0.f;

#pragma unroll
        for (int ks = 0; ks < 8; ks++) {
            int kb = ks * 8;
            uint32_t ah[4], al[4];
            ah[0] = sAh2[ r0      * P2 + kb + t];
            ah[1] = sAh2[(r0 + 8) * P2 + kb + t];
            ah[2] = sAh2[ r0      * P2 + kb + 4 + t];
            ah[3] = sAh2[(r0 + 8) * P2 + kb + 4 + t];
            al[0] = sAl2[ r0      * P2 + kb + t];
            al[1] = sAl2[(r0 + 8) * P2 + kb + t];
            al[2] = sAl2[ r0      * P2 + kb + 4 + t];
            al[3] = sAl2[(r0 + 8) * P2 + kb + 4 + t];
#pragma unroll
            for (int nt = 0; nt < 8; nt++) {
                int n = nt * 8 + gid;
                uint32_t bh[2], bl[2];
                bh[0] = sBh2[n * P2 + kb + t];
                bh[1] = sBh2[n * P2 + kb + 4 + t];
                bl[0] = sBl2[n * P2 + kb + t];
                bl[1] = sBl2[n * P2 + kb + 4 + t];
                mma_bf16(acc[nt], ah, bh);
                mma_bf16(acc[nt], ah, bl);
                mma_bf16(acc[nt], al, bh);
            }
        }

#pragma unroll
        for (int nt = 0; nt < 8; nt++) {
            int col = nt * 8 + t * 2;
            if (node0 < N)
                *reinterpret_cast<uint32_t*>(yh + (size_t)node0 * 64 + col) = pack_h2(acc[nt][0], acc[nt][1]);
            if (node1 < N)
                *reinterpret_cast<uint32_t*>(yh + (size_t)node1 * 64 + col) = pack_h2(acc[nt][2], acc[nt][3]);
        }
    }
}

// ---------------- fp16-payload pull: one warp/node, quarter-warp per edge row ----------------
// EPI: 0 = fp32 store to o1 (agg)
//      1 = h = relu(acc*nd + b); o1 = h (fp32); o2 = (h*ns) fp16 payload
//      2 = o1 = acc + b (fp32 output)
template<int EPI>
__global__ void __launch_bounds__(256)
pull_h16_kernel(const __half* __restrict__ tab,
                const int* __restrict__ rowptr, const int* __restrict__ colidx,
                const float* __restrict__ ns, const float* __restrict__ nd,
                const float* __restrict__ b,
                float* __restrict__ o1, __half* __restrict__ o2, int N) {
    int node = (blockIdx.x * blockDim.x + threadIdx.x) >> 5;
    if (node >= N) return;
    const int lane = threadIdx.x & 31;
    const int grp = lane >> 3;
    const int q   = lane & 7;
    const int beg = __ldg(&rowptr[node]);
    const int deg = __ldg(&rowptr[node + 1]) - beg;

    float acc[8];
#pragma unroll
    for (int j = 0; j < 8; j++) acc[j] = 0.f;

    int i = 0;
    while (i < deg) {
        int rem   = deg - i;
        int chunk = (rem < 32) ? rem : 32;
        int my = __ldg(&colidx[beg + i + ((lane < chunk) ? lane : 0)]);
        int nq = (chunk + 3) >> 2;
#pragma unroll 4
        for (int p = 0; p < nq; p++) {
            int j = 4 * p + grp;
            bool act = (j < chunk);
            int s = __shfl_sync(0xffffffffu, my, act ? j : 0);
            uint4 v = *reinterpret_cast<const uint4*>(tab + (size_t)s * 64 + q * 8);
            if (act) {
                const __half2* hp = reinterpret_cast<const __half2*>(&v);
                float2 f0 = __half22float2(hp[0]);
                float2 f1 = __half22float2(hp[1]);
                float2 f2 = __half22float2(hp[2]);
                float2 f3 = __half22float2(hp[3]);
                acc[0] += f0.x; acc[1] += f0.y;
                acc[2] += f1.x; acc[3] += f1.y;
                acc[4] += f2.x; acc[5] += f2.y;
                acc[6] += f3.x; acc[7] += f3.y;
            }
        }
        i += chunk;
    }

#pragma unroll
    for (int j = 0; j < 8; j++) {
        acc[j] += __shfl_xor_sync(0xffffffffu, acc[j], 8);
        acc[j] += __shfl_xor_sync(0xffffffffu, acc[j], 16);
    }
    if (grp != 0) return;

    float* o1p = o1 + (size_t)node * 64 + q * 8;
    if (EPI == 0) {
        reinterpret_cast<float4*>(o1p)[0] = make_float4(acc[0], acc[1], acc[2], acc[3]);
        reinterpret_cast<float4*>(o1p)[1] = make_float4(acc[4], acc[5], acc[6], acc[7]);
    } else if (EPI == 1) {
        float d = nd[node];
        float4 b0 = reinterpret_cast<const float4*>(b + q * 8)[0];
        float4 b1 = reinterpret_cast<const float4*>(b + q * 8)[1];
        float h[8];
        h[0] = fmaxf(fmaf(acc[0], d, b0.x), 0.f);
        h[1] = fmaxf(fmaf(acc[1], d, b0.y), 0.f);
        h[2] = fmaxf(fmaf(acc[2], d, b0.z), 0.f);
        h[3] = fmaxf(fmaf(acc[3], d, b0.w), 0.f);
        h[4] = fmaxf(fmaf(acc[4], d, b1.x), 0.f);
        h[5] = fmaxf(fmaf(acc[5], d, b1.y), 0.f);
        h[6] = fmaxf(fmaf(acc[6], d, b1.z), 0.f);
        h[7] = fmaxf(fmaf(acc[7], d, b1.w), 0.f);
        reinterpret_cast<float4*>(o1p)[0] = make_float4(h[0], h[1], h[2], h[3]);
        reinterpret_cast<float4*>(o1p)[1] = make_float4(h[4], h[5], h[6], h[7]);
        float sn = ns[node];
        uint4 pk;
        pk.x = pack_h2(h[0] * sn, h[1] * sn);
        pk.y = pack_h2(h[2] * sn, h[3] * sn);
        pk.z = pack_h2(h[4] * sn, h[5] * sn);
        pk.w = pack_h2(h[6] * sn, h[7] * sn);
        *reinterpret_cast<uint4*>(o2 + (size_t)node * 64 + q * 8) = pk;
    } else {
        float4 b0 = reinterpret_cast<const float4*>(b + q * 8)[0];
        float4 b1 = reinterpret_cast<const float4*>(b + q * 8)[1];
        reinterpret_cast<float4*>(o1p)[0] =
            make_float4(acc[0] + b0.x, acc[1] + b0.y, acc[2] + b0.z, acc[3] + b0.w);
        reinterpret_cast<float4*>(o1p)[1] =
            make_float4(acc[4] + b1.x, acc[5] + b1.y, acc[6] + b1.z, acc[7] + b1.w);
    }
}

// ---------------- launch ----------------

extern "C" void kernel_launch(void* const* d_in, const int* in_sizes, int n_in,
                              void* d_out, int out_size) {
    const float* feats = (const float*)d_in[0];
    const int*   src   = (const int*)  d_in[1];
    const int*   dst   = (const int*)  d_in[2];
    const float* W1    = (const float*)d_in[3];
    const float* b1    = (const float*)d_in[4];
    const float* W2    = (const float*)d_in[5];
    const float* b2    = (const float*)d_in[6];
    const float* Wout  = (const float*)d_in[7];
    const float* bout  = (const float*)d_in[8];
    float* out = (float*)d_out;

    const int N = in_sizes[0] / 128;
    const int E = in_sizes[1];

    int *p_degin, *p_degout, *p_rowptr, *p_cursor, *p_bsum, *p_colidx;
    float *p_ns, *p_nd, *p_h1, *p_agg;
    __half *p_preh, *p_h1nh, *p_yh;
    cudaGetSymbolAddress((void**)&p_degin,  g_degin);
    cudaGetSymbolAddress((void**)&p_degout, g_degout);
    cudaGetSymbolAddress((void**)&p_rowptr, g_rowptr);
    cudaGetSymbolAddress((void**)&p_cursor, g_cursor);
    cudaGetSymbolAddress((void**)&p_bsum,   g_bsum);
    cudaGetSymbolAddress((void**)&p_colidx, g_colidx);
    cudaGetSymbolAddress((void**)&p_ns,     g_ns);
    cudaGetSymbolAddress((void**)&p_nd,     g_nd);
    cudaGetSymbolAddress((void**)&p_preh,   g_preh);
    cudaGetSymbolAddress((void**)&p_h1nh,   g_h1nh);
    cudaGetSymbolAddress((void**)&p_yh,     g_yh);
    cudaGetSymbolAddress((void**)&p_h1,     g_h1);
    cudaGetSymbolAddress((void**)&p_agg,    g_agg);

    const int TB = 256;
    auto cdiv = [](long long a, long long b) { return (unsigned)((a + b - 1) / b); };
    const int nb = (int)cdiv(N, 512);        // <= 256 for N <= 131072

    const int SMEM_BIG = 384 * (128 / 2 + 4) * 4;   // 104448
    cudaFuncSetAttribute(gemm1_kernel,  cudaFuncAttributeMaxDynamicSharedMemorySize, SMEM_BIG);
    cudaFuncSetAttribute(gemm23_kernel, cudaFuncAttributeMaxDynamicSharedMemorySize, SMEM_BIG);

    // 1-5: degrees, norms, CSR
    zero_deg_kernel<<<cdiv(N, TB), TB>>>(p_degin, p_degout, N);
    degree_kernel  <<<cdiv(cdiv(E, 2), TB), TB>>>(src, dst, p_degout, p_degin, E);
    scan1_kernel   <<<nb, 512>>>(p_degin, p_degout, p_rowptr, p_bsum, p_ns, p_nd, N);
    scan3_kernel   <<<cdiv(N, TB), TB>>>(p_rowptr, p_cursor, p_bsum, nb, N, E);
    csrfill_kernel <<<cdiv(cdiv(E, 2), TB), TB>>>(src, dst, p_cursor, p_colidx, E);

    const unsigned mmaGrid  = cdiv(N, 128);
    const unsigned pullGrid = cdiv((long long)N * 32, TB);

    // 6: preh = (feats*ns)@W1 (fp16)
    gemm1_kernel<<<mmaGrid, TB, SMEM_BIG>>>(feats, W1, p_ns, p_preh, N);
    // 7: h1 = relu(pull(preh)*nd + b1); h1nh = (h1*ns) fp16
    pull_h16_kernel<1><<<pullGrid, TB>>>(p_preh, p_rowptr, p_colidx, p_ns, p_nd, b1, p_h1, p_h1nh, N);
    // 8: agg = pull(h1nh)
    pull_h16_kernel<0><<<pullGrid, TB>>>(p_h1nh, p_rowptr, p_colidx, nullptr, nullptr, nullptr, p_agg, nullptr, N);
    // 9: h2 = relu((agg@W2)*nd+b2) [regs]; yh = [h1|h2]@Wout (fp16)
    gemm23_kernel<<<mmaGrid, TB, SMEM_BIG>>>(p_agg, p_h1, W2, b2, p_nd, Wout, p_yh, N);
    // 10: out = pull(yh) + bout
    pull_h16_kernel<2><<<pullGrid, TB>>>(p_yh, p_rowptr, p_colidx, nullptr, nullptr, bout, out, nullptr, N);
}

// round 15
// speedup vs baseline: 1.1416x; 1.0407x over previous
#include <cuda_runtime.h>
#include <cuda_bf16.h>
#include <cuda_fp16.h>
#include <cstdint>

#define NMAX 100000
#define EMAX 1600000

// ---------------- scratch (static device globals; no allocation) ----------------
__device__ int   g_degin [NMAX];
__device__ int   g_degout[NMAX];
__device__ float g_ns [NMAX];     // deg_out^-1/2
__device__ float g_rns[NMAX];     // deg_out^+1/2  (1/ns)
__device__ float g_nd [NMAX];     // deg_in^-1/2
__device__ int   g_rowptr[NMAX + 1];
__device__ int   g_cursor[NMAX];
__device__ int   g_bsum[256];
__device__ int   g_colidx[EMAX];
__device__ __align__(256) __half g_preh[NMAX * 64];   // fp16 pull payloads / tables
__device__ __align__(256) __half g_h1nh[NMAX * 64];   // fp16( h1 * ns )
__device__ __align__(256) __half g_aggh[NMAX * 64];   // fp16( segsum(h1nh[src]) )
__device__ __align__(256) __half g_yh  [NMAX * 64];

// pack two floats -> fp16x2 in a uint32
__device__ __forceinline__ uint32_t pack_h2(float a, float b) {
    uint32_t lo = (uint32_t)__half_as_ushort(__float2half_rn(a));
    uint32_t hi = (uint32_t)__half_as_ushort(__float2half_rn(b));
    return lo | (hi << 16);
}

// ---------------- small kernels ----------------

__global__ void zero_deg_kernel(int* __restrict__ a, int* __restrict__ b, int N) {
    int i = blockIdx.x * blockDim.x + threadIdx.x;
    if (i < N) { a[i] = 0; b[i] = 0; }
}

// 2 edges per thread via int2 loads
__global__ void degree_kernel(const int* __restrict__ src, const int* __restrict__ dst,
                              int* __restrict__ dout, int* __restrict__ din, int E) {
    int i = blockIdx.x * blockDim.x + threadIdx.x;
    int e0 = i * 2;
    if (e0 + 1 < E) {
        int2 s2 = *reinterpret_cast<const int2*>(src + e0);
        int2 d2 = *reinterpret_cast<const int2*>(dst + e0);
        atomicAdd(&dout[s2.x], 1);
        atomicAdd(&dout[s2.y], 1);
        atomicAdd(&din [d2.x], 1);
        atomicAdd(&din [d2.y], 1);
    } else if (e0 < E) {
        atomicAdd(&dout[src[e0]], 1);
        atomicAdd(&din [dst[e0]], 1);
    }
}

// block-level exclusive scan of deg_in -> rowptr partials + block sums; fused norms
__global__ void scan1_kernel(const int* __restrict__ degin, const int* __restrict__ degout,
                             int* __restrict__ rowptr, int* __restrict__ bsum,
                             float* __restrict__ ns, float* __restrict__ rns,
                             float* __restrict__ nd, int N) {
    __shared__ int s[512];
    int t = threadIdx.x;
    int i = blockIdx.x * 512 + t;
    int v = (i < N) ? degin[i] : 0;
    s[t] = v; __syncthreads();
    for (int off = 1; off < 512; off <<= 1) {
        int u = (t >= off) ? s[t - off] : 0;
        __syncthreads();
        s[t] += u;
        __syncthreads();
    }
    if (i < N) {
        rowptr[i] = s[t] - v;
        nd[i] = rsqrtf((float)max(v, 1));
        float dg = (float)max(degout[i], 1);
        ns[i]  = rsqrtf(dg);
        rns[i] = sqrtf(dg);
    }
    if (t == 511) bsum[blockIdx.x] = s[511];
}

// finalize rowptr: every block scans the (<=256) block sums locally, applies offset
__global__ void scan3_kernel(int* __restrict__ rowptr, int* __restrict__ cursor,
                             const int* __restrict__ bsum, int nb, int N, int E) {
    __shared__ int sb[256];
    int t = threadIdx.x;
    int v = (t < nb) ? bsum[t] : 0;
    sb[t] = v; __syncthreads();
    for (int off = 1; off < 256; off <<= 1) {
        int u = (t >= off) ? sb[t - off] : 0;
        __syncthreads();
        sb[t] += u;
        __syncthreads();
    }
    int ex = sb[t] - v;
    __syncthreads();
    sb[t] = ex;
    __syncthreads();
    int i = blockIdx.x * blockDim.x + threadIdx.x;
    if (i < N) {
        int r = rowptr[i] + sb[i >> 9];
        rowptr[i] = r;
        cursor[i] = r;
    }
    if (i == 0) rowptr[N] = E;
}

// 2 edges per thread via int2 loads
__global__ void csrfill_kernel(const int* __restrict__ src, const int* __restrict__ dst,
                               int* __restrict__ cursor, int* __restrict__ colidx, int E) {
    int i = blockIdx.x * blockDim.x + threadIdx.x;
    int e0 = i * 2;
    if (e0 + 1 < E) {
        int2 s2 = *reinterpret_cast<const int2*>(src + e0);
        int2 d2 = *reinterpret_cast<const int2*>(dst + e0);
        int slot0 = atomicAdd(&cursor[d2.x], 1);
        colidx[slot0] = s2.x;
        int slot1 = atomicAdd(&cursor[d2.y], 1);
        colidx[slot1] = s2.y;
    } else if (e0 < E) {
        int slot = atomicAdd(&cursor[dst[e0]], 1);
        colidx[slot] = src[e0];
    }
}

// ================= split-bf16 mma.sync GEMM pieces (compute_100-legal) =================

__device__ __forceinline__ void mma_bf16(float* c, const uint32_t* a, const uint32_t* b) {
    asm volatile(
        "mma.sync.aligned.m16n8k16.row.col.f32.bf16.bf16.f32 "
        "{%0,%1,%2,%3}, {%4,%5,%6,%7}, {%8,%9}, {%0,%1,%2,%3};"
        : "+f"(c[0]), "+f"(c[1]), "+f"(c[2]), "+f"(c[3])
        : "r"(a[0]), "r"(a[1]), "r"(a[2]), "r"(a[3]), "r"(b[0]), "r"(b[1]));
}

__device__ __forceinline__ void cvt_pair(float f0, float f1, uint32_t& hi, uint32_t& lo) {
    __nv_bfloat16 h0 = __float2bfloat16(f0);
    __nv_bfloat16 h1 = __float2bfloat16(f1);
    __nv_bfloat16 l0 = __float2bfloat16(f0 - __bfloat162float(h0));
    __nv_bfloat16 l1 = __float2bfloat16(f1 - __bfloat162float(h1));
    hi = (uint32_t)__bfloat16_as_ushort(h0) | ((uint32_t)__bfloat16_as_ushort(h1) << 16);
    lo = (uint32_t)__bfloat16_as_ushort(l0) | ((uint32_t)__bfloat16_as_ushort(l1) << 16);
}

// layer-1 GEMM: preh[N,64] = fp16( (feats*ns)[N,128] @ W1[128,64] )
__global__ void __launch_bounds__(256)
gemm1_kernel(const float* __restrict__ A, const float* __restrict__ W,
             const float* __restrict__ ns, __half* __restrict__ outh, int N) {
    extern __shared__ uint32_t sm[];
    constexpr int K = 128, P = K / 2 + 4, K4 = K / 4;
    uint32_t* sAh = sm;
    uint32_t* sAl = sm + 128 * P;
    uint32_t* sBh = sm + 256 * P;
    uint32_t* sBl = sm + 256 * P + 64 * P;

    const int tid = threadIdx.x;
    const int wid = tid >> 5, lane = tid & 31;
    const int gid = lane >> 2, t = lane & 3;
    const int n0 = blockIdx.x * 128;

    for (int idx = tid; idx < 128 * K4; idx += 256) {
        int m = idx / K4, f = idx % K4;
        int node = n0 + m;
        float4 v = make_float4(0.f, 0.f, 0.f, 0.f);
        if (node < N) {
            v = reinterpret_cast<const float4*>(A + (size_t)node * K)[f];
            float s = ns[node];
            v.x *= s; v.y *= s; v.z *= s; v.w *= s;
        }
        uint32_t h0, l0, h1, l1;
        cvt_pair(v.x, v.y, h0, l0);
        cvt_pair(v.z, v.w, h1, l1);
        int o = m * P + f * 2;
        sAh[o] = h0; sAh[o + 1] = h1;
        sAl[o] = l0; sAl[o + 1] = l1;
    }
    for (int idx = tid; idx < 64 * (K / 2); idx += 256) {
        int n = idx & 63, kp = idx >> 6;
        uint32_t h, l;
        cvt_pair(W[(size_t)(2 * kp) * 64 + n], W[(size_t)(2 * kp + 1) * 64 + n], h, l);
        sBh[n * P + kp] = h; sBl[n * P + kp] = l;
    }
    __syncthreads();

    float acc[8][4];
#pragma unroll
    for (int nt = 0; nt < 8; nt++)
#pragma unroll
        for (int j = 0; j < 4; j++) acc[nt][j] = 0.f;

    const int r0 = wid * 16 + gid;
#pragma unroll
    for (int ks = 0; ks < K / 16; ks++) {
        int kb = ks * 8;
        uint32_t ah[4], al[4];
        ah[0] = sAh[ r0      * P + kb + t];
        ah[1] = sAh[(r0 + 8) * P + kb + t];
        ah[2] = sAh[ r0      * P + kb + 4 + t];
        ah[3] = sAh[(r0 + 8) * P + kb + 4 + t];
        al[0] = sAl[ r0      * P + kb + t];
        al[1] = sAl[(r0 + 8) * P + kb + t];
        al[2] = sAl[ r0      * P + kb + 4 + t];
        al[3] = sAl[(r0 + 8) * P + kb + 4 + t];
#pragma unroll
        for (int nt = 0; nt < 8; nt++) {
            int n = nt * 8 + gid;
            uint32_t bh[2], bl[2];
            bh[0] = sBh[n * P + kb + t];
            bh[1] = sBh[n * P + kb + 4 + t];
            bl[0] = sBl[n * P + kb + t];
            bl[1] = sBl[n * P + kb + 4 + t];
            mma_bf16(acc[nt], ah, bh);
            mma_bf16(acc[nt], ah, bl);
            mma_bf16(acc[nt], al, bh);
        }
    }

    const int node0 = n0 + r0, node1 = node0 + 8;
#pragma unroll
    for (int nt = 0; nt < 8; nt++) {
        int col = nt * 8 + t * 2;
        if (node0 < N)
            *reinterpret_cast<uint32_t*>(outh + (size_t)node0 * 64 + col) = pack_h2(acc[nt][0], acc[nt][1]);
        if (node1 < N)
            *reinterpret_cast<uint32_t*>(outh + (size_t)node1 * 64 + col) = pack_h2(acc[nt][2], acc[nt][3]);
    }
}

// fused layers 2+3: h2 = relu((aggh@W2)*nd + b2) [kept in regs];
//                   yh = fp16( [h1nh*rns | h2] @ Wout )
__global__ void __launch_bounds__(256)
gemm23_kernel(const __half* __restrict__ aggh, const __half* __restrict__ h1nh,
              const float* __restrict__ rns,
              const float* __restrict__ W2, const float* __restrict__ b2,
              const float* __restrict__ nd, const float* __restrict__ Wout,
              __half* __restrict__ yh, int N) {
    extern __shared__ uint32_t sm[];
    constexpr int P1 = 64 / 2 + 4;    // 36
    constexpr int P2 = 128 / 2 + 4;   // 68

    const int tid = threadIdx.x;
    const int wid = tid >> 5, lane = tid & 31;
    const int gid = lane >> 2, t = lane & 3;
    const int n0 = blockIdx.x * 128;
    const int r0 = wid * 16 + gid;
    const int node0 = n0 + r0, node1 = node0 + 8;

    // ---------- phase 1: acc = aggh @ W2  (K=64, fp16 A source) ----------
    {
        uint32_t* sAh = sm;
        uint32_t* sAl = sm + 128 * P1;
        uint32_t* sBh = sm + 256 * P1;
        uint32_t* sBl = sm + 256 * P1 + 64 * P1;

        for (int idx = tid; idx < 128 * 8; idx += 256) {
            int m = idx >> 3, u = idx & 7;      // u: uint4 (8 halves) within the 64-half row
            int node = n0 + m;
            uint4 v = make_uint4(0u, 0u, 0u, 0u);
            if (node < N)
                v = *reinterpret_cast<const uint4*>(aggh + (size_t)node * 64 + u * 8);
            const __half2* hp = reinterpret_cast<const __half2*>(&v);
#pragma unroll
            for (int j = 0; j < 4; j++) {
                float2 f = __half22float2(hp[j]);
                uint32_t h, l;
                cvt_pair(f.x, f.y, h, l);
                int o = m * P1 + u * 4 + j;
                sAh[o] = h; sAl[o] = l;
            }
        }
        for (int idx = tid; idx < 64 * 32; idx += 256) {
            int n = idx & 63, kp = idx >> 6;
            uint32_t h, l;
            cvt_pair(W2[(size_t)(2 * kp) * 64 + n], W2[(size_t)(2 * kp + 1) * 64 + n], h, l);
            sBh[n * P1 + kp] = h; sBl[n * P1 + kp] = l;
        }
        __syncthreads();

        float acc[8][4];
#pragma unroll
        for (int nt = 0; nt < 8; nt++)
#pragma unroll
            for (int j = 0; j < 4; j++) acc[nt][j] = 0.f;

#pragma unroll
        for (int ks = 0; ks < 4; ks++) {
            int kb = ks * 8;
            uint32_t ah[4], al[4];
            ah[0] = sAh[ r0      * P1 + kb + t];
            ah[1] = sAh[(r0 + 8) * P1 + kb + t];
            ah[2] = sAh[ r0      * P1 + kb + 4 + t];
            ah[3] = sAh[(r0 + 8) * P1 + kb + 4 + t];
            al[0] = sAl[ r0      * P1 + kb + t];
            al[1] = sAl[(r0 + 8) * P1 + kb + t];
            al[2] = sAl[ r0      * P1 + kb + 4 + t];
            al[3] = sAl[(r0 + 8) * P1 + kb + 4 + t];
#pragma unroll
            for (int nt = 0; nt < 8; nt++) {
                int n = nt * 8 + gid;
                uint32_t bh[2], bl[2];
                bh[0] = sBh[n * P1 + kb + t];
                bh[1] = sBh[n * P1 + kb + 4 + t];
                bl[0] = sBl[n * P1 + kb + t];
                bl[1] = sBl[n * P1 + kb + 4 + t];
                mma_bf16(acc[nt], ah, bh);
                mma_bf16(acc[nt], ah, bl);
                mma_bf16(acc[nt], al, bh);
            }
        }

        // epilogue: h2 = relu(acc*nd + b2), restage into phase-2 A (k = 64+col)
        float d0 = (node0 < N) ? nd[node0] : 0.f;
        float d1 = (node1 < N) ? nd[node1] : 0.f;
        float h2v[8][4];
#pragma unroll
        for (int nt = 0; nt < 8; nt++) {
            int col = nt * 8 + t * 2;
            float2 bb = *reinterpret_cast<const float2*>(b2 + col);
            h2v[nt][0] = fmaxf(fmaf(acc[nt][0], d0, bb.x), 0.f);
            h2v[nt][1] = fmaxf(fmaf(acc[nt][1], d0, bb.y), 0.f);
            h2v[nt][2] = fmaxf(fmaf(acc[nt][2], d1, bb.x), 0.f);
            h2v[nt][3] = fmaxf(fmaf(acc[nt][3], d1, bb.y), 0.f);
        }
        __syncthreads();   // phase-1 smem reads done; safe to overwrite

        // ---------- phase 2 staging ----------
        uint32_t* sAh2 = sm;
        uint32_t* sAl2 = sm + 128 * P2;
        uint32_t* sBh2 = sm + 256 * P2;
        uint32_t* sBl2 = sm + 256 * P2 + 64 * P2;

        // h1 part (k 0..63): h1 = h1nh * rns[node]
        for (int idx = tid; idx < 128 * 8; idx += 256) {
            int m = idx >> 3, u = idx & 7;
            int node = n0 + m;
            uint4 v = make_uint4(0u, 0u, 0u, 0u);
            float r = 0.f;
            if (node < N) {
                v = *reinterpret_cast<const uint4*>(h1nh + (size_t)node * 64 + u * 8);
                r = rns[node];
            }
            const __half2* hp = reinterpret_cast<const __half2*>(&v);
#pragma unroll
            for (int j = 0; j < 4; j++) {
                float2 f = __half22float2(hp[j]);
                uint32_t h, l;
                cvt_pair(f.x * r, f.y * r, h, l);
                int o = m * P2 + u * 4 + j;
                sAh2[o] = h; sAl2[o] = l;
            }
        }
        // h2 part from registers (k 64..127 -> kp 32..63)
#pragma unroll
        for (int nt = 0; nt < 8; nt++) {
            int kp = 32 + nt * 4 + t;
            uint32_t h, l;
            cvt_pair(h2v[nt][0], h2v[nt][1], h, l);
            sAh2[r0 * P2 + kp] = h; sAl2[r0 * P2 + kp] = l;
            cvt_pair(h2v[nt][2], h2v[nt][3], h, l);
            sAh2[(r0 + 8) * P2 + kp] = h; sAl2[(r0 + 8) * P2 + kp] = l;
        }
        // B = Wout^T (K=128)
        for (int idx = tid; idx < 64 * 64; idx += 256) {
            int n = idx & 63, kp = idx >> 6;
            uint32_t h, l;
            cvt_pair(Wout[(size_t)(2 * kp) * 64 + n], Wout[(size_t)(2 * kp + 1) * 64 + n], h, l);
            sBh2[n * P2 + kp] = h; sBl2[n * P2 + kp] = l;
        }
        __syncthreads();

        // ---------- phase 2 MMA: y = [h1|h2] @ Wout ----------
#pragma unroll
        for (int nt = 0; nt < 8; nt++)
#pragma unroll
            for (int j = 0; j < 4; j++) acc[nt][j] = 0.f;

#pragma unroll
        for (int ks = 0; ks < 8; ks++) {
            int kb = ks * 8;
            uint32_t ah[4], al[4];
            ah[0] = sAh2[ r0      * P2 + kb + t];
            ah[1] = sAh2[(r0 + 8) * P2 + kb + t];
            ah[2] = sAh2[ r0      * P2 + kb + 4 + t];
            ah[3] = sAh2[(r0 + 8) * P2 + kb + 4 + t];
            al[0] = sAl2[ r0      * P2 + kb + t];
            al[1] = sAl2[(r0 + 8) * P2 + kb + t];
            al[2] = sAl2[ r0      * P2 + kb + 4 + t];
            al[3] = sAl2[(r0 + 8) * P2 + kb + 4 + t];
#pragma unroll
            for (int nt = 0; nt < 8; nt++) {
                int n = nt * 8 + gid;
                uint32_t bh[2], bl[2];
                bh[0] = sBh2[n * P2 + kb + t];
                bh[1] = sBh2[n * P2 + kb + 4 + t];
                bl[0] = sBl2[n * P2 + kb + t];
                bl[1] = sBl2[n * P2 + kb + 4 + t];
                mma_bf16(acc[nt], ah, bh);
                mma_bf16(acc[nt], ah, bl);
                mma_bf16(acc[nt], al, bh);
            }
        }

#pragma unroll
        for (int nt = 0; nt < 8; nt++) {
            int col = nt * 8 + t * 2;
            if (node0 < N)
                *reinterpret_cast<uint32_t*>(yh + (size_t)node0 * 64 + col) = pack_h2(acc[nt][0], acc[nt][1]);
            if (node1 < N)
                *reinterpret_cast<uint32_t*>(yh + (size_t)node1 * 64 + col) = pack_h2(acc[nt][2], acc[nt][3]);
        }
    }
}

// ---------------- fp16-payload pull: one warp/node, quarter-warp per edge row ----------------
// EPI: 0 = o2 = acc (fp16)
//      1 = h = relu(acc*nd + b); o2 = (h*ns) fp16   (h1 itself is never materialized)
//      2 = o1 = acc + b (fp32 output)
template<int EPI>
__global__ void __launch_bounds__(256)
pull_h16_kernel(const __half* __restrict__ tab,
                const int* __restrict__ rowptr, const int* __restrict__ colidx,
                const float* __restrict__ ns, const float* __restrict__ nd,
                const float* __restrict__ b,
                float* __restrict__ o1, __half* __restrict__ o2, int N) {
    int node = (blockIdx.x * blockDim.x + threadIdx.x) >> 5;
    if (node >= N) return;
    const int lane = threadIdx.x & 31;
    const int grp = lane >> 3;
    const int q   = lane & 7;
    const int beg = __ldg(&rowptr[node]);
    const int deg = __ldg(&rowptr[node + 1]) - beg;

    float acc[8];
#pragma unroll
    for (int j = 0; j < 8; j++) acc[j] = 0.f;

    int i = 0;
    while (i < deg) {
        int rem   = deg - i;
        int chunk = (rem < 32) ? rem : 32;
        int my = __ldg(&colidx[beg + i + ((lane < chunk) ? lane : 0)]);
        int nq = (chunk + 3) >> 2;
#pragma unroll 4
        for (int p = 0; p < nq; p++) {
            int j = 4 * p + grp;
            bool act = (j < chunk);
            int s = __shfl_sync(0xffffffffu, my, act ? j : 0);
            uint4 v = *reinterpret_cast<const uint4*>(tab + (size_t)s * 64 + q * 8);
            if (act) {
                const __half2* hp = reinterpret_cast<const __half2*>(&v);
                float2 f0 = __half22float2(hp[0]);
                float2 f1 = __half22float2(hp[1]);
                float2 f2 = __half22float2(hp[2]);
                float2 f3 = __half22float2(hp[3]);
                acc[0] += f0.x; acc[1] += f0.y;
                acc[2] += f1.x; acc[3] += f1.y;
                acc[4] += f2.x; acc[5] += f2.y;
                acc[6] += f3.x; acc[7] += f3.y;
            }
        }
        i += chunk;
    }

#pragma unroll
    for (int j = 0; j < 8; j++) {
        acc[j] += __shfl_xor_sync(0xffffffffu, acc[j], 8);
        acc[j] += __shfl_xor_sync(0xffffffffu, acc[j], 16);
    }
    if (grp != 0) return;

    if (EPI == 0) {
        uint4 pk;
        pk.x = pack_h2(acc[0], acc[1]);
        pk.y = pack_h2(acc[2], acc[3]);
        pk.z = pack_h2(acc[4], acc[5]);
        pk.w = pack_h2(acc[6], acc[7]);
        *reinterpret_cast<uint4*>(o2 + (size_t)node * 64 + q * 8) = pk;
    } else if (EPI == 1) {
        float d = nd[node];
        float4 b0 = reinterpret_cast<const float4*>(b + q * 8)[0];
        float4 b1 = reinterpret_cast<const float4*>(b + q * 8)[1];
        float sn = ns[node];
        float h[8];
        h[0] = fmaxf(fmaf(acc[0], d, b0.x), 0.f) * sn;
        h[1] = fmaxf(fmaf(acc[1], d, b0.y), 0.f) * sn;
        h[2] = fmaxf(fmaf(acc[2], d, b0.z), 0.f) * sn;
        h[3] = fmaxf(fmaf(acc[3], d, b0.w), 0.f) * sn;
        h[4] = fmaxf(fmaf(acc[4], d, b1.x), 0.f) * sn;
        h[5] = fmaxf(fmaf(acc[5], d, b1.y), 0.f) * sn;
        h[6] = fmaxf(fmaf(acc[6], d, b1.z), 0.f) * sn;
        h[7] = fmaxf(fmaf(acc[7], d, b1.w), 0.f) * sn;
        uint4 pk;
        pk.x = pack_h2(h[0], h[1]);
        pk.y = pack_h2(h[2], h[3]);
        pk.z = pack_h2(h[4], h[5]);
        pk.w = pack_h2(h[6], h[7]);
        *reinterpret_cast<uint4*>(o2 + (size_t)node * 64 + q * 8) = pk;
    } else {
        float4 b0 = reinterpret_cast<const float4*>(b + q * 8)[0];
        float4 b1 = reinterpret_cast<const float4*>(b + q * 8)[1];
        float* o1p = o1 + (size_t)node * 64 + q * 8;
        reinterpret_cast<float4*>(o1p)[0] =
            make_float4(acc[0] + b0.x, acc[1] + b0.y, acc[2] + b0.z, acc[3] + b0.w);
        reinterpret_cast<float4*>(o1p)[1] =
            make_float4(acc[4] + b1.x, acc[5] + b1.y, acc[6] + b1.z, acc[7] + b1.w);
    }
}

// ---------------- launch ----------------

extern "C" void kernel_launch(void* const* d_in, const int* in_sizes, int n_in,
                              void* d_out, int out_size) {
    const float* feats = (const float*)d_in[0];
    const int*   src   = (const int*)  d_in[1];
    const int*   dst   = (const int*)  d_in[2];
    const float* W1    = (const float*)d_in[3];
    const float* b1    = (const float*)d_in[4];
    const float* W2    = (const float*)d_in[5];
    const float* b2    = (const float*)d_in[6];
    const float* Wout  = (const float*)d_in[7];
    const float* bout  = (const float*)d_in[8];
    float* out = (float*)d_out;

    const int N = in_sizes[0] / 128;
    const int E = in_sizes[1];

    int *p_degin, *p_degout, *p_rowptr, *p_cursor, *p_bsum, *p_colidx;
    float *p_ns, *p_rns, *p_nd;
    __half *p_preh, *p_h1nh, *p_aggh, *p_yh;
    cudaGetSymbolAddress((void**)&p_degin,  g_degin);
    cudaGetSymbolAddress((void**)&p_degout, g_degout);
    cudaGetSymbolAddress((void**)&p_rowptr, g_rowptr);
    cudaGetSymbolAddress((void**)&p_cursor, g_cursor);
    cudaGetSymbolAddress((void**)&p_bsum,   g_bsum);
    cudaGetSymbolAddress((void**)&p_colidx, g_colidx);
    cudaGetSymbolAddress((void**)&p_ns,     g_ns);
    cudaGetSymbolAddress((void**)&p_rns,    g_rns);
    cudaGetSymbolAddress((void**)&p_nd,     g_nd);
    cudaGetSymbolAddress((void**)&p_preh,   g_preh);
    cudaGetSymbolAddress((void**)&p_h1nh,   g_h1nh);
    cudaGetSymbolAddress((void**)&p_aggh,   g_aggh);
    cudaGetSymbolAddress((void**)&p_yh,     g_yh);

    const int TB = 256;
    auto cdiv = [](long long a, long long b) { return (unsigned)((a + b - 1) / b); };
    const int nb = (int)cdiv(N, 512);        // <= 256 for N <= 131072

    const int SMEM_BIG = 384 * (128 / 2 + 4) * 4;   // 104448
    cudaFuncSetAttribute(gemm1_kernel,  cudaFuncAttributeMaxDynamicSharedMemorySize, SMEM_BIG);
    cudaFuncSetAttribute(gemm23_kernel, cudaFuncAttributeMaxDynamicSharedMemorySize, SMEM_BIG);

    // 1-5: degrees, norms, CSR
    zero_deg_kernel<<<cdiv(N, TB), TB>>>(p_degin, p_degout, N);
    degree_kernel  <<<cdiv(cdiv(E, 2), TB), TB>>>(src, dst, p_degout, p_degin, E);
    scan1_kernel   <<<nb, 512>>>(p_degin, p_degout, p_rowptr, p_bsum, p_ns, p_rns, p_nd, N);
    scan3_kernel   <<<cdiv(N, TB), TB>>>(p_rowptr, p_cursor, p_bsum, nb, N, E);
    csrfill_kernel <<<cdiv(cdiv(E, 2), TB), TB>>>(src, dst, p_cursor, p_colidx, E);

    const unsigned mmaGrid  = cdiv(N, 128);
    const unsigned pullGrid = cdiv((long long)N * 32, TB);

    // 6: preh = (feats*ns)@W1 (fp16)
    gemm1_kernel<<<mmaGrid, TB, SMEM_BIG>>>(feats, W1, p_ns, p_preh, N);
    // 7: h1nh = fp16( relu(pull(preh)*nd + b1) * ns )   (h1 never materialized)
    pull_h16_kernel<1><<<pullGrid, TB>>>(p_preh, p_rowptr, p_colidx, p_ns, p_nd, b1, nullptr, p_h1nh, N);
    // 8: aggh = fp16( pull(h1nh) )
    pull_h16_kernel<0><<<pullGrid, TB>>>(p_h1nh, p_rowptr, p_colidx, nullptr, nullptr, nullptr, nullptr, p_aggh, N);
    // 9: h2 = relu((aggh@W2)*nd+b2) [regs]; yh = [h1nh*rns | h2]@Wout (fp16)
    gemm23_kernel<<<mmaGrid, TB, SMEM_BIG>>>(p_aggh, p_h1nh, p_rns, W2, b2, p_nd, Wout, p_yh, N);
    // 10: out = pull(yh) + bout
    pull_h16_kernel<2><<<pullGrid, TB>>>(p_yh, p_rowptr, p_colidx, nullptr, nullptr, bout, out, nullptr, N);
}